// round 9
// baseline (speedup 1.0000x reference)
#include <cuda_runtime.h>
#include <cuda_bf16.h>
#include <math.h>
#include <stdint.h>

// Qwen2.5 MoE expert router — Round 9: bf16x3-split warp HMMA GEMM + fused
// softmax/top-2/dispatch + last-block aux loss, with deterministic exact-fp32
// rescue for tokens whose top-k margin is within HMMA noise.
// out layout (fp32, reference return order):
//   [0, NE) dispatch | [NE, 2NE) combine | [2NE, 3NE) logits | [3NE, 4NE) probs
//   [4NE] aux_loss | [4NE+1, +2N) top_k_idx (float) | next 2N: top_k_probs_norm

#define D_DIM 2048
#define E_DIM 64
#define BM 128
#define BKT 64                 // K elements per smem tile
#define NKT (D_DIM / BKT)      // 32 k-tiles
#define NTHREADS 256
#define L_STRIDE (E_DIM + 1)
#define GAP_TH 2e-4f           // prob-margin below which we recompute in fp32

#define ROW_BYTES 144          // 128B data + 16B pad: ldmatrix & STS conflict-free
#define SA_OFF(s) ((s) * (BM * ROW_BYTES))
#define SB_OFF(s) (3 * BM * ROW_BYTES + (s) * (E_DIM * ROW_BYTES))
#define DSMEM_BYTES (3 * BM * ROW_BYTES + 3 * E_DIM * ROW_BYTES)   // 82944

__device__ __forceinline__ uint32_t smem_u32(const void* p) {
    uint32_t a;
    asm("{ .reg .u64 t; cvta.to.shared.u64 t, %1; cvt.u32.u64 %0, t; }" : "=r"(a) : "l"(p));
    return a;
}
__device__ __forceinline__ void ldsm_x4(uint32_t& r0, uint32_t& r1, uint32_t& r2,
                                        uint32_t& r3, uint32_t addr) {
    asm volatile("ldmatrix.sync.aligned.m8n8.x4.shared.b16 {%0,%1,%2,%3}, [%4];"
                 : "=r"(r0), "=r"(r1), "=r"(r2), "=r"(r3) : "r"(addr));
}
__device__ __forceinline__ void mma_bf16(float& d0, float& d1, float& d2, float& d3,
                                         uint32_t a0, uint32_t a1, uint32_t a2, uint32_t a3,
                                         uint32_t b0, uint32_t b1) {
    asm volatile("mma.sync.aligned.m16n8k16.row.col.f32.bf16.bf16.f32 "
                 "{%0,%1,%2,%3}, {%4,%5,%6,%7}, {%8,%9}, {%0,%1,%2,%3};"
                 : "+f"(d0), "+f"(d1), "+f"(d2), "+f"(d3)
                 : "r"(a0), "r"(a1), "r"(a2), "r"(a3), "r"(b0), "r"(b1));
}
__device__ __forceinline__ uint32_t pack_bf16x2(float lo, float hi) {
    uint32_t r;
    asm("cvt.rn.bf16x2.f32 %0, %1, %2;" : "=r"(r) : "f"(hi), "f"(lo));
    return r;
}

__device__ __align__(16) __nv_bfloat16 g_w0[E_DIM * D_DIM];
__device__ __align__(16) __nv_bfloat16 g_w1[E_DIM * D_DIM];
__device__ __align__(16) __nv_bfloat16 g_w2[E_DIM * D_DIM];
__device__ float g_partials[128 * E_DIM];
__device__ unsigned int g_count = 0;

__global__ void w_split_kernel(const float* __restrict__ w) {
    int i = blockIdx.x * blockDim.x + threadIdx.x;
    if (i < E_DIM * D_DIM) {
        float f = w[i];
        uint32_t u = __float_as_uint(f);
        uint32_t b0 = u & 0xFFFF0000u;
        float t = f - __uint_as_float(b0);                   // exact
        uint32_t b1 = __float_as_uint(t) & 0xFFFF0000u;
        float r = t - __uint_as_float(b1);                   // exact
        g_w0[i] = __ushort_as_bfloat16((unsigned short)(b0 >> 16));
        g_w1[i] = __ushort_as_bfloat16((unsigned short)(b1 >> 16));
        g_w2[i] = __float2bfloat16_rn(r);
    }
}

__global__ __launch_bounds__(NTHREADS, 1)
void router_fused_kernel(const float* __restrict__ x,
                         const float* __restrict__ w,
                         float* __restrict__ out,
                         int N)
{
    extern __shared__ char dsmem[];
    __shared__ float sPart[8 * E_DIM];
    __shared__ int sIsLast;

    const uint32_t smem_b = smem_u32(dsmem);
    const int tid = threadIdx.x;
    const int wid = tid >> 5;
    const int lane = tid & 31;
    const int n0 = blockIdx.x * BM;

    const int mw = wid & 3;   // warp M index (32 rows)
    const int nw = wid >> 2;  // warp N index (32 cols)

    const uint32_t aRow = (uint32_t)((mw * 32 + (lane & 15)) * ROW_BYTES
                                     + (lane >> 4) * 16);
    const uint32_t bRowIdx = (uint32_t)(((lane >> 4) & 1) * 8 + (lane & 7));
    const uint32_t bKoff = (uint32_t)(((lane >> 3) & 1) * 16);

    float4 v[8];
    uint4 bq0[2], bq1[2], bq2[2];

    float acc[2][4][4];
    #pragma unroll
    for (int i = 0; i < 2; i++)
        #pragma unroll
        for (int j = 0; j < 4; j++)
            #pragma unroll
            for (int q = 0; q < 4; q++) acc[i][j][q] = 0.f;

    const uint4* __restrict__ w0v = reinterpret_cast<const uint4*>(g_w0);
    const uint4* __restrict__ w1v = reinterpret_cast<const uint4*>(g_w1);
    const uint4* __restrict__ w2v = reinterpret_cast<const uint4*>(g_w2);

    // ---- prologue: stage tile 0 ----
    #pragma unroll
    for (int p = 0; p < 8; p++) {
        int idx = tid + 256 * p;
        int row = idx >> 4, c4 = idx & 15;
        int n = n0 + row; if (n > N - 1) n = N - 1;
        v[p] = *reinterpret_cast<const float4*>(x + (size_t)n * D_DIM + c4 * 4);
    }
    #pragma unroll
    for (int q = 0; q < 2; q++) {
        int idx = tid + 256 * q;
        int er = idx >> 3, c16 = idx & 7;
        int gi = er * (D_DIM / 8) + c16;
        bq0[q] = w0v[gi]; bq1[q] = w1v[gi]; bq2[q] = w2v[gi];
    }

    for (int kt = 0; kt < NKT; kt++) {
        __syncthreads();

        // ---- convert + store A (bf16x3 split), store B ----
        char* sA0 = dsmem + SA_OFF(0);
        char* sA1 = dsmem + SA_OFF(1);
        char* sA2 = dsmem + SA_OFF(2);
        #pragma unroll
        for (int p = 0; p < 8; p++) {
            int idx = tid + 256 * p;
            int row = idx >> 4, c4 = idx & 15;
            float4 f = v[p];
            uint32_t u0 = __float_as_uint(f.x), u1 = __float_as_uint(f.y),
                     u2 = __float_as_uint(f.z), u3 = __float_as_uint(f.w);
            uint32_t hiA = __byte_perm(u0, u1, 0x7632);
            uint32_t hiB = __byte_perm(u2, u3, 0x7632);
            float t0 = f.x - __uint_as_float(u0 & 0xFFFF0000u);
            float t1 = f.y - __uint_as_float(u1 & 0xFFFF0000u);
            float t2 = f.z - __uint_as_float(u2 & 0xFFFF0000u);
            float t3 = f.w - __uint_as_float(u3 & 0xFFFF0000u);
            uint32_t s0 = __float_as_uint(t0), s1 = __float_as_uint(t1),
                     s2 = __float_as_uint(t2), s3 = __float_as_uint(t3);
            uint32_t miA = __byte_perm(s0, s1, 0x7632);
            uint32_t miB = __byte_perm(s2, s3, 0x7632);
            float r0 = t0 - __uint_as_float(s0 & 0xFFFF0000u);
            float r1 = t1 - __uint_as_float(s1 & 0xFFFF0000u);
            float r2 = t2 - __uint_as_float(s2 & 0xFFFF0000u);
            float r3 = t3 - __uint_as_float(s3 & 0xFFFF0000u);
            uint32_t loA = pack_bf16x2(r0, r1);
            uint32_t loB = pack_bf16x2(r2, r3);
            uint32_t off = (uint32_t)(row * ROW_BYTES + c4 * 8);
            *reinterpret_cast<uint2*>(sA0 + off) = make_uint2(hiA, hiB);
            *reinterpret_cast<uint2*>(sA1 + off) = make_uint2(miA, miB);
            *reinterpret_cast<uint2*>(sA2 + off) = make_uint2(loA, loB);
        }
        char* sB0 = dsmem + SB_OFF(0);
        char* sB1 = dsmem + SB_OFF(1);
        char* sB2 = dsmem + SB_OFF(2);
        #pragma unroll
        for (int q = 0; q < 2; q++) {
            int idx = tid + 256 * q;
            int er = idx >> 3, c16 = idx & 7;
            uint32_t off = (uint32_t)(er * ROW_BYTES + c16 * 16);
            *reinterpret_cast<uint4*>(sB0 + off) = bq0[q];
            *reinterpret_cast<uint4*>(sB1 + off) = bq1[q];
            *reinterpret_cast<uint4*>(sB2 + off) = bq2[q];
        }
        __syncthreads();

        // ---- prefetch next tile ----
        if (kt + 1 < NKT) {
            const int kbase = (kt + 1) * BKT;
            #pragma unroll
            for (int p = 0; p < 8; p++) {
                int idx = tid + 256 * p;
                int row = idx >> 4, c4 = idx & 15;
                int n = n0 + row; if (n > N - 1) n = N - 1;
                v[p] = *reinterpret_cast<const float4*>(x + (size_t)n * D_DIM + kbase + c4 * 4);
            }
            #pragma unroll
            for (int q = 0; q < 2; q++) {
                int idx = tid + 256 * q;
                int er = idx >> 3, c16 = idx & 7;
                int gi = er * (D_DIM / 8) + (kt + 1) * 8 + c16;
                bq0[q] = w0v[gi]; bq1[q] = w1v[gi]; bq2[q] = w2v[gi];
            }
        }

        // ---- 6 split-products x 4 k16-steps ----
        const uint32_t aBase[3] = { smem_b + SA_OFF(0) + aRow,
                                    smem_b + SA_OFF(1) + aRow,
                                    smem_b + SA_OFF(2) + aRow };
        const uint32_t bBase0 = (uint32_t)((nw * 32 + bRowIdx) * ROW_BYTES) + bKoff;
        const uint32_t bBase[3] = { smem_b + SB_OFF(0) + bBase0,
                                    smem_b + SB_OFF(1) + bBase0,
                                    smem_b + SB_OFF(2) + bBase0 };
        const int sa[6] = {0, 0, 1, 1, 0, 2};
        const int sb[6] = {0, 1, 0, 1, 2, 0};

        #pragma unroll
        for (int t = 0; t < 6; t++) {
            const uint32_t ab = aBase[sa[t]];
            const uint32_t bb = bBase[sb[t]];
            #pragma unroll
            for (int j = 0; j < 4; j++) {
                uint32_t a0[4], a1[4], bA[4], bB[4];
                ldsm_x4(a0[0], a0[1], a0[2], a0[3], ab + j * 32);
                ldsm_x4(a1[0], a1[1], a1[2], a1[3], ab + j * 32 + 16 * ROW_BYTES);
                ldsm_x4(bA[0], bA[1], bA[2], bA[3], bb + j * 32);
                ldsm_x4(bB[0], bB[1], bB[2], bB[3], bb + j * 32 + 16 * ROW_BYTES);
                mma_bf16(acc[0][0][0], acc[0][0][1], acc[0][0][2], acc[0][0][3],
                         a0[0], a0[1], a0[2], a0[3], bA[0], bA[1]);
                mma_bf16(acc[0][1][0], acc[0][1][1], acc[0][1][2], acc[0][1][3],
                         a0[0], a0[1], a0[2], a0[3], bA[2], bA[3]);
                mma_bf16(acc[0][2][0], acc[0][2][1], acc[0][2][2], acc[0][2][3],
                         a0[0], a0[1], a0[2], a0[3], bB[0], bB[1]);
                mma_bf16(acc[0][3][0], acc[0][3][1], acc[0][3][2], acc[0][3][3],
                         a0[0], a0[1], a0[2], a0[3], bB[2], bB[3]);
                mma_bf16(acc[1][0][0], acc[1][0][1], acc[1][0][2], acc[1][0][3],
                         a1[0], a1[1], a1[2], a1[3], bA[0], bA[1]);
                mma_bf16(acc[1][1][0], acc[1][1][1], acc[1][1][2], acc[1][1][3],
                         a1[0], a1[1], a1[2], a1[3], bA[2], bA[3]);
                mma_bf16(acc[1][2][0], acc[1][2][1], acc[1][2][2], acc[1][2][3],
                         a1[0], a1[1], a1[2], a1[3], bB[0], bB[1]);
                mma_bf16(acc[1][3][0], acc[1][3][1], acc[1][3][2], acc[1][3][3],
                         a1[0], a1[1], a1[2], a1[3], bB[2], bB[3]);
            }
        }
    }

    // ---- accumulators -> smem logits ----
    __syncthreads();
    float* Lg = reinterpret_cast<float*>(dsmem);
    {
        int rb = mw * 32 + (lane >> 2);
        int cb = nw * 32 + 2 * (lane & 3);
        #pragma unroll
        for (int ti = 0; ti < 2; ti++)
            #pragma unroll
            for (int tj = 0; tj < 4; tj++) {
                int r = rb + ti * 16;
                int c = cb + tj * 8;
                Lg[r * L_STRIDE + c]            = acc[ti][tj][0];
                Lg[r * L_STRIDE + c + 1]        = acc[ti][tj][1];
                Lg[(r + 8) * L_STRIDE + c]      = acc[ti][tj][2];
                Lg[(r + 8) * L_STRIDE + c + 1]  = acc[ti][tj][3];
            }
    }
    __syncthreads();

    // ---- softmax / top-2 / scatter, with exact-fp32 rescue ----
    const size_t NE = (size_t)N * E_DIM;
    const float NEG_INF = __int_as_float(0xff800000);
    float auxA = 0.f, auxB = 0.f;

    for (int tk = wid; tk < BM; tk += 8) {
        int n = n0 + tk;
        if (n >= N) continue;  // warp-uniform

        float v0 = Lg[tk * L_STRIDE + lane];
        float v1 = Lg[tk * L_STRIDE + lane + 32];

        float p0, p1, bvv, sv; int bi, si;

        for (int pass = 0; pass < 2; pass++) {
            float mx = fmaxf(v0, v1);
            #pragma unroll
            for (int o = 16; o; o >>= 1) mx = fmaxf(mx, __shfl_xor_sync(0xffffffffu, mx, o));
            float x0 = expf(v0 - mx), x1 = expf(v1 - mx);
            float s = x0 + x1;
            #pragma unroll
            for (int o = 16; o; o >>= 1) s += __shfl_xor_sync(0xffffffffu, s, o);
            p0 = x0 / s; p1 = x1 / s;

            // top-1 (tie -> smallest index)
            if (p0 >= p1) { bvv = p0; bi = lane; } else { bvv = p1; bi = lane + 32; }
            #pragma unroll
            for (int o = 16; o; o >>= 1) {
                float ov = __shfl_xor_sync(0xffffffffu, bvv, o);
                int   oi = __shfl_xor_sync(0xffffffffu, bi, o);
                if (ov > bvv || (ov == bvv && oi < bi)) { bvv = ov; bi = oi; }
            }
            // top-2
            float c0 = (lane == bi) ? NEG_INF : p0;
            float c1 = (lane + 32 == bi) ? NEG_INF : p1;
            if (c0 >= c1) { sv = c0; si = lane; } else { sv = c1; si = lane + 32; }
            #pragma unroll
            for (int o = 16; o; o >>= 1) {
                float ov = __shfl_xor_sync(0xffffffffu, sv, o);
                int   oi = __shfl_xor_sync(0xffffffffu, si, o);
                if (ov > sv || (ov == sv && oi < si)) { sv = ov; si = oi; }
            }
            if (pass == 1) break;

            // top-3 value (for margin check)
            float e0 = (lane == bi || lane == si) ? NEG_INF : p0;
            float e1 = (lane + 32 == bi || lane + 32 == si) ? NEG_INF : p1;
            float tv = fmaxf(e0, e1);
            #pragma unroll
            for (int o = 16; o; o >>= 1) tv = fmaxf(tv, __shfl_xor_sync(0xffffffffu, tv, o));

            if (bvv - sv >= GAP_TH && sv - tv >= GAP_TH) break;  // margins safe

            // ---- exact fp32 recompute (ascending-k fmaf order == R3 order) ----
            {
                const float4* xr  = reinterpret_cast<const float4*>(x + (size_t)n * D_DIM);
                const float4* wr0 = reinterpret_cast<const float4*>(w + (size_t)lane * D_DIM);
                const float4* wr1 = reinterpret_cast<const float4*>(w + (size_t)(lane + 32) * D_DIM);
                float l0 = 0.f, l1 = 0.f;
                #pragma unroll 4
                for (int k4 = 0; k4 < D_DIM / 4; k4++) {
                    float4 xv = __ldg(xr + k4);
                    float4 a  = __ldg(wr0 + k4);
                    float4 b  = __ldg(wr1 + k4);
                    l0 = fmaf(xv.x, a.x, l0); l0 = fmaf(xv.y, a.y, l0);
                    l0 = fmaf(xv.z, a.z, l0); l0 = fmaf(xv.w, a.w, l0);
                    l1 = fmaf(xv.x, b.x, l1); l1 = fmaf(xv.y, b.y, l1);
                    l1 = fmaf(xv.z, b.z, l1); l1 = fmaf(xv.w, b.w, l1);
                }
                v0 = l0; v1 = l1;   // loop back: redo softmax + top-2 on exact logits
            }
        }

        auxA += p0; auxB += p1;

        float tsum = bvv + sv;
        float pn1 = bvv / tsum, pn2 = sv / tsum;

        size_t rowL = (size_t)n * E_DIM;
        out[2 * NE + rowL + lane]      = v0;
        out[2 * NE + rowL + lane + 32] = v1;
        out[3 * NE + rowL + lane]      = p0;
        out[3 * NE + rowL + lane + 32] = p1;
        float d0 = (lane == bi) ? pn1 : ((lane == si) ? pn2 : 0.f);
        float d1 = (lane + 32 == bi) ? pn1 : ((lane + 32 == si) ? pn2 : 0.f);
        out[rowL + lane]           = d0;
        out[rowL + lane + 32]      = d1;
        out[NE + rowL + lane]      = d0;
        out[NE + rowL + lane + 32] = d1;
        if (lane == 0) {
            size_t o5 = 4 * NE + 1 + (size_t)n * 2;
            out[o5]     = (float)bi;
            out[o5 + 1] = (float)si;
            size_t o6 = 4 * NE + 1 + (size_t)N * 2 + (size_t)n * 2;
            out[o6]     = pn1;
            out[o6 + 1] = pn2;
        }
    }

    // ---- per-block expert prob sums + last-block aux loss ----
    sPart[wid * E_DIM + lane]      = auxA;
    sPart[wid * E_DIM + lane + 32] = auxB;
    __syncthreads();
    if (tid < E_DIM) {
        float ssum = 0.f;
        #pragma unroll
        for (int wd = 0; wd < 8; wd++) ssum += sPart[wd * E_DIM + tid];
        g_partials[blockIdx.x * E_DIM + tid] = ssum;
    }
    __threadfence();
    if (tid == 0) {
        unsigned int prev = atomicAdd(&g_count, 1u);
        sIsLast = (prev == (unsigned int)(gridDim.x - 1)) ? 1 : 0;
    }
    __syncthreads();

    if (sIsLast) {
        __threadfence();
        const int nBlocks = gridDim.x;
        int e = tid & 63;
        int q = tid >> 6;
        float s = 0.f;
        for (int b = q; b < nBlocks; b += 4) s += g_partials[b * E_DIM + e];
        sPart[q * E_DIM + e] = s;
        __syncthreads();
        if (tid < E_DIM) {
            float t = sPart[0 * E_DIM + tid] + sPart[1 * E_DIM + tid]
                    + sPart[2 * E_DIM + tid] + sPart[3 * E_DIM + tid];
            float m = t / (float)N;
            Lg[tid] = m * m;
        }
        __syncthreads();
        if (tid == 0) {
            float a = 0.f;
            #pragma unroll
            for (int i = 0; i < E_DIM; i++) a += Lg[i];
            out[4 * NE] = a;   // mean_e(E*pbar^2) = sum_e pbar^2
            g_count = 0;       // reset for graph replay
        }
    }
}

extern "C" void kernel_launch(void* const* d_in, const int* in_sizes, int n_in,
                              void* d_out, int out_size)
{
    const float* x = (const float*)d_in[0];   // [N, 2048]
    const float* w = (const float*)d_in[1];   // [64, 2048]
    float* out = (float*)d_out;

    int N = in_sizes[0] / D_DIM;              // 16384
    int nBlocks = (N + BM - 1) / BM;          // 128

    cudaFuncSetAttribute(router_fused_kernel,
                         cudaFuncAttributeMaxDynamicSharedMemorySize, DSMEM_BYTES);

    w_split_kernel<<<(E_DIM * D_DIM + 255) / 256, 256>>>(w);
    router_fused_kernel<<<nBlocks, NTHREADS, DSMEM_BYTES>>>(x, w, out, N);
}

// round 10
// speedup vs baseline: 2.5716x; 2.5716x over previous
#include <cuda_runtime.h>
#include <cuda_bf16.h>
#include <math.h>
#include <stdint.h>

// Qwen2.5 MoE expert router — Round 10: two-kernel design.
//  K1: bf16x3-split warp HMMA GEMM -> writes fp32 logits directly to out[2NE..3NE).
//  K2: epilogue — softmax/top-2/dispatch/aux from logits, with cheap exact-fp32
//      top-4 re-ordering rescue for near-tied tokens (ordering only).
// out layout (fp32, reference return order):
//   [0, NE) dispatch | [NE, 2NE) combine | [2NE, 3NE) logits | [3NE, 4NE) probs
//   [4NE] aux_loss | [4NE+1, +2N) top_k_idx (float) | next 2N: top_k_probs_norm

#define D_DIM 2048
#define E_DIM 64
#define BM 128
#define NKT (D_DIM / 64)       // 32 k-tiles of 64
#define NTHREADS 256
#define GAP_TH 1e-4f           // prob margin below which ordering is re-derived in fp32

#define ROW_BYTES 144          // 128B data + 16B pad: ldmatrix & STS conflict-free
#define SA_OFF(s) ((s) * (BM * ROW_BYTES))
#define SB_OFF(s) (3 * BM * ROW_BYTES + (s) * (E_DIM * ROW_BYTES))
#define DSMEM_BYTES (3 * BM * ROW_BYTES + 3 * E_DIM * ROW_BYTES)   // 82944

__device__ __forceinline__ uint32_t smem_u32(const void* p) {
    uint32_t a;
    asm("{ .reg .u64 t; cvta.to.shared.u64 t, %1; cvt.u32.u64 %0, t; }" : "=r"(a) : "l"(p));
    return a;
}
__device__ __forceinline__ void ldsm_x4(uint32_t& r0, uint32_t& r1, uint32_t& r2,
                                        uint32_t& r3, uint32_t addr) {
    asm volatile("ldmatrix.sync.aligned.m8n8.x4.shared.b16 {%0,%1,%2,%3}, [%4];"
                 : "=r"(r0), "=r"(r1), "=r"(r2), "=r"(r3) : "r"(addr));
}
__device__ __forceinline__ void mma_bf16(float& d0, float& d1, float& d2, float& d3,
                                         uint32_t a0, uint32_t a1, uint32_t a2, uint32_t a3,
                                         uint32_t b0, uint32_t b1) {
    asm volatile("mma.sync.aligned.m16n8k16.row.col.f32.bf16.bf16.f32 "
                 "{%0,%1,%2,%3}, {%4,%5,%6,%7}, {%8,%9}, {%0,%1,%2,%3};"
                 : "+f"(d0), "+f"(d1), "+f"(d2), "+f"(d3)
                 : "r"(a0), "r"(a1), "r"(a2), "r"(a3), "r"(b0), "r"(b1));
}
__device__ __forceinline__ uint32_t pack_bf16x2(float lo, float hi) {
    uint32_t r;
    asm("cvt.rn.bf16x2.f32 %0, %1, %2;" : "=r"(r) : "f"(hi), "f"(lo));
    return r;
}

__device__ __align__(16) __nv_bfloat16 g_w0[E_DIM * D_DIM];
__device__ __align__(16) __nv_bfloat16 g_w1[E_DIM * D_DIM];
__device__ __align__(16) __nv_bfloat16 g_w2[E_DIM * D_DIM];
__device__ float g_partials[128 * E_DIM];
__device__ unsigned int g_count = 0;

__global__ void w_split_kernel(const float* __restrict__ w) {
    int i = blockIdx.x * blockDim.x + threadIdx.x;
    if (i < E_DIM * D_DIM) {
        float f = w[i];
        uint32_t u = __float_as_uint(f);
        uint32_t b0 = u & 0xFFFF0000u;
        float t = f - __uint_as_float(b0);                   // exact
        uint32_t b1 = __float_as_uint(t) & 0xFFFF0000u;
        float r = t - __uint_as_float(b1);                   // exact
        g_w0[i] = __ushort_as_bfloat16((unsigned short)(b0 >> 16));
        g_w1[i] = __ushort_as_bfloat16((unsigned short)(b1 >> 16));
        g_w2[i] = __float2bfloat16_rn(r);
    }
}

// ================= Kernel 1: GEMM (logits only) =================
__global__ __launch_bounds__(NTHREADS, 1)
void router_gemm_kernel(const float* __restrict__ x,
                        float* __restrict__ out,
                        int N)
{
    extern __shared__ char dsmem[];
    const uint32_t smem_b = smem_u32(dsmem);
    const int tid = threadIdx.x;
    const int wid = tid >> 5;
    const int lane = tid & 31;
    const int n0 = blockIdx.x * BM;

    const int mw = wid & 3;   // 4 warps along M (32 rows each)
    const int nw = wid >> 2;  // 2 warps along N (32 cols each)

    const uint32_t aRow = (uint32_t)((mw * 32 + (lane & 15)) * ROW_BYTES
                                     + (lane >> 4) * 16);
    const uint32_t bRowIdx = (uint32_t)(((lane >> 4) & 1) * 8 + (lane & 7));
    const uint32_t bKoff = (uint32_t)(((lane >> 3) & 1) * 16);

    float4 v[8];
    uint4 bq0[2], bq1[2], bq2[2];

    float acc[2][4][4];
    #pragma unroll
    for (int i = 0; i < 2; i++)
        #pragma unroll
        for (int j = 0; j < 4; j++)
            #pragma unroll
            for (int q = 0; q < 4; q++) acc[i][j][q] = 0.f;

    const uint4* __restrict__ w0v = reinterpret_cast<const uint4*>(g_w0);
    const uint4* __restrict__ w1v = reinterpret_cast<const uint4*>(g_w1);
    const uint4* __restrict__ w2v = reinterpret_cast<const uint4*>(g_w2);

    // prologue: stage tile 0
    #pragma unroll
    for (int p = 0; p < 8; p++) {
        int idx = tid + 256 * p;
        int row = idx >> 4, c4 = idx & 15;
        int n = n0 + row; if (n > N - 1) n = N - 1;
        v[p] = *reinterpret_cast<const float4*>(x + (size_t)n * D_DIM + c4 * 4);
    }
    #pragma unroll
    for (int q = 0; q < 2; q++) {
        int idx = tid + 256 * q;
        int er = idx >> 3, c16 = idx & 7;
        int gi = er * (D_DIM / 8) + c16;
        bq0[q] = w0v[gi]; bq1[q] = w1v[gi]; bq2[q] = w2v[gi];
    }

    for (int kt = 0; kt < NKT; kt++) {
        __syncthreads();

        char* sA0 = dsmem + SA_OFF(0);
        char* sA1 = dsmem + SA_OFF(1);
        char* sA2 = dsmem + SA_OFF(2);
        #pragma unroll
        for (int p = 0; p < 8; p++) {
            int idx = tid + 256 * p;
            int row = idx >> 4, c4 = idx & 15;
            float4 f = v[p];
            uint32_t u0 = __float_as_uint(f.x), u1 = __float_as_uint(f.y),
                     u2 = __float_as_uint(f.z), u3 = __float_as_uint(f.w);
            uint32_t hiA = __byte_perm(u0, u1, 0x7632);
            uint32_t hiB = __byte_perm(u2, u3, 0x7632);
            float t0 = f.x - __uint_as_float(u0 & 0xFFFF0000u);
            float t1 = f.y - __uint_as_float(u1 & 0xFFFF0000u);
            float t2 = f.z - __uint_as_float(u2 & 0xFFFF0000u);
            float t3 = f.w - __uint_as_float(u3 & 0xFFFF0000u);
            uint32_t s0 = __float_as_uint(t0), s1 = __float_as_uint(t1),
                     s2 = __float_as_uint(t2), s3 = __float_as_uint(t3);
            uint32_t miA = __byte_perm(s0, s1, 0x7632);
            uint32_t miB = __byte_perm(s2, s3, 0x7632);
            float r0 = t0 - __uint_as_float(s0 & 0xFFFF0000u);
            float r1 = t1 - __uint_as_float(s1 & 0xFFFF0000u);
            float r2 = t2 - __uint_as_float(s2 & 0xFFFF0000u);
            float r3 = t3 - __uint_as_float(s3 & 0xFFFF0000u);
            uint32_t loA = pack_bf16x2(r0, r1);
            uint32_t loB = pack_bf16x2(r2, r3);
            uint32_t off = (uint32_t)(row * ROW_BYTES + c4 * 8);
            *reinterpret_cast<uint2*>(sA0 + off) = make_uint2(hiA, hiB);
            *reinterpret_cast<uint2*>(sA1 + off) = make_uint2(miA, miB);
            *reinterpret_cast<uint2*>(sA2 + off) = make_uint2(loA, loB);
        }
        char* sB0 = dsmem + SB_OFF(0);
        char* sB1 = dsmem + SB_OFF(1);
        char* sB2 = dsmem + SB_OFF(2);
        #pragma unroll
        for (int q = 0; q < 2; q++) {
            int idx = tid + 256 * q;
            int er = idx >> 3, c16 = idx & 7;
            uint32_t off = (uint32_t)(er * ROW_BYTES + c16 * 16);
            *reinterpret_cast<uint4*>(sB0 + off) = bq0[q];
            *reinterpret_cast<uint4*>(sB1 + off) = bq1[q];
            *reinterpret_cast<uint4*>(sB2 + off) = bq2[q];
        }
        __syncthreads();

        if (kt + 1 < NKT) {
            const int kbase = (kt + 1) * 64;
            #pragma unroll
            for (int p = 0; p < 8; p++) {
                int idx = tid + 256 * p;
                int row = idx >> 4, c4 = idx & 15;
                int n = n0 + row; if (n > N - 1) n = N - 1;
                v[p] = *reinterpret_cast<const float4*>(x + (size_t)n * D_DIM + kbase + c4 * 4);
            }
            #pragma unroll
            for (int q = 0; q < 2; q++) {
                int idx = tid + 256 * q;
                int er = idx >> 3, c16 = idx & 7;
                int gi = er * (D_DIM / 8) + (kt + 1) * 8 + c16;
                bq0[q] = w0v[gi]; bq1[q] = w1v[gi]; bq2[q] = w2v[gi];
            }
        }

        const uint32_t aBase[3] = { smem_b + SA_OFF(0) + aRow,
                                    smem_b + SA_OFF(1) + aRow,
                                    smem_b + SA_OFF(2) + aRow };
        const uint32_t bBase0 = (uint32_t)((nw * 32 + bRowIdx) * ROW_BYTES) + bKoff;
        const uint32_t bBase[3] = { smem_b + SB_OFF(0) + bBase0,
                                    smem_b + SB_OFF(1) + bBase0,
                                    smem_b + SB_OFF(2) + bBase0 };
        const int sa[6] = {0, 0, 1, 1, 0, 2};
        const int sb[6] = {0, 1, 0, 1, 2, 0};

        #pragma unroll
        for (int t = 0; t < 6; t++) {
            const uint32_t ab = aBase[sa[t]];
            const uint32_t bb = bBase[sb[t]];
            #pragma unroll
            for (int j = 0; j < 4; j++) {
                uint32_t a0[4], a1[4], bA[4], bB[4];
                ldsm_x4(a0[0], a0[1], a0[2], a0[3], ab + j * 32);
                ldsm_x4(a1[0], a1[1], a1[2], a1[3], ab + j * 32 + 16 * ROW_BYTES);
                ldsm_x4(bA[0], bA[1], bA[2], bA[3], bb + j * 32);
                ldsm_x4(bB[0], bB[1], bB[2], bB[3], bb + j * 32 + 16 * ROW_BYTES);
                mma_bf16(acc[0][0][0], acc[0][0][1], acc[0][0][2], acc[0][0][3],
                         a0[0], a0[1], a0[2], a0[3], bA[0], bA[1]);
                mma_bf16(acc[0][1][0], acc[0][1][1], acc[0][1][2], acc[0][1][3],
                         a0[0], a0[1], a0[2], a0[3], bA[2], bA[3]);
                mma_bf16(acc[0][2][0], acc[0][2][1], acc[0][2][2], acc[0][2][3],
                         a0[0], a0[1], a0[2], a0[3], bB[0], bB[1]);
                mma_bf16(acc[0][3][0], acc[0][3][1], acc[0][3][2], acc[0][3][3],
                         a0[0], a0[1], a0[2], a0[3], bB[2], bB[3]);
                mma_bf16(acc[1][0][0], acc[1][0][1], acc[1][0][2], acc[1][0][3],
                         a1[0], a1[1], a1[2], a1[3], bA[0], bA[1]);
                mma_bf16(acc[1][1][0], acc[1][1][1], acc[1][1][2], acc[1][1][3],
                         a1[0], a1[1], a1[2], a1[3], bA[2], bA[3]);
                mma_bf16(acc[1][2][0], acc[1][2][1], acc[1][2][2], acc[1][2][3],
                         a1[0], a1[1], a1[2], a1[3], bB[0], bB[1]);
                mma_bf16(acc[1][3][0], acc[1][3][1], acc[1][3][2], acc[1][3][3],
                         a1[0], a1[1], a1[2], a1[3], bB[2], bB[3]);
            }
        }
    }

    // write logits directly from fragments: out[2NE + n*64 + c]
    const size_t NE = (size_t)N * E_DIM;
    float* Lout = out + 2 * NE;
    int rb = mw * 32 + (lane >> 2);
    int cb = nw * 32 + 2 * (lane & 3);
    #pragma unroll
    for (int ti = 0; ti < 2; ti++)
        #pragma unroll
        for (int tj = 0; tj < 4; tj++) {
            int r = rb + ti * 16;
            int c = cb + tj * 8;
            *reinterpret_cast<float2*>(Lout + (size_t)(n0 + r) * E_DIM + c) =
                make_float2(acc[ti][tj][0], acc[ti][tj][1]);
            *reinterpret_cast<float2*>(Lout + (size_t)(n0 + r + 8) * E_DIM + c) =
                make_float2(acc[ti][tj][2], acc[ti][tj][3]);
        }
}

// ================= Kernel 2: epilogue =================
__global__ __launch_bounds__(NTHREADS)
void router_epilogue_kernel(const float* __restrict__ x,
                            const float* __restrict__ w,
                            float* __restrict__ out,
                            int N)
{
    __shared__ float sPart[8 * E_DIM];
    __shared__ int sIsLast;

    const int tid = threadIdx.x;
    const int wid = tid >> 5;
    const int lane = tid & 31;
    const int n0 = blockIdx.x * BM;
    const size_t NE = (size_t)N * E_DIM;
    const float* __restrict__ Lin = out + 2 * NE;
    const float NEG_INF = __int_as_float(0xff800000);
    const unsigned FULL = 0xffffffffu;

    float auxA = 0.f, auxB = 0.f;

    for (int tk = wid; tk < BM; tk += 8) {
        int n = n0 + tk;
        if (n >= N) continue;  // warp-uniform

        float v0 = Lin[(size_t)n * E_DIM + lane];
        float v1 = Lin[(size_t)n * E_DIM + lane + 32];

        float mx = fmaxf(v0, v1);
        #pragma unroll
        for (int o = 16; o; o >>= 1) mx = fmaxf(mx, __shfl_xor_sync(FULL, mx, o));
        float x0 = expf(v0 - mx), x1 = expf(v1 - mx);
        float s = x0 + x1;
        #pragma unroll
        for (int o = 16; o; o >>= 1) s += __shfl_xor_sync(FULL, s, o);
        float p0 = x0 / s, p1 = x1 / s;
        auxA += p0; auxB += p1;

        // argmax helper (value desc, index asc on ties), ranks 1..4
        int cid[4]; float cv[4];
        float m0v = p0, m1v = p1;
        #pragma unroll
        for (int rko = 0; rko < 4; rko++) {
            float bv; int bix;
            if (m0v >= m1v) { bv = m0v; bix = lane; } else { bv = m1v; bix = lane + 32; }
            #pragma unroll
            for (int o = 16; o; o >>= 1) {
                float ov = __shfl_xor_sync(FULL, bv, o);
                int   oi = __shfl_xor_sync(FULL, bix, o);
                if (ov > bv || (ov == bv && oi < bix)) { bv = ov; bix = oi; }
            }
            cv[rko] = bv; cid[rko] = bix;
            if (lane == bix) m0v = NEG_INF;
            if (lane + 32 == bix) m1v = NEG_INF;
        }

        int bi = cid[0], si = cid[1];
        float bvv = cv[0], sv = cv[1];

        // rescue: exact fp32 ordering of top-4 when margins are tight (warp-uniform)
        if (cv[0] - cv[1] < GAP_TH || cv[1] - cv[2] < GAP_TH || cv[2] - cv[3] < GAP_TH) {
            float ex[4] = {0.f, 0.f, 0.f, 0.f};
            const float* xr = x + (size_t)n * D_DIM + lane;
            const float* w0r = w + (size_t)cid[0] * D_DIM + lane;
            const float* w1r = w + (size_t)cid[1] * D_DIM + lane;
            const float* w2r = w + (size_t)cid[2] * D_DIM + lane;
            const float* w3r = w + (size_t)cid[3] * D_DIM + lane;
            #pragma unroll 4
            for (int m = 0; m < D_DIM / 32; m++) {
                float xv = __ldg(xr + 32 * m);
                ex[0] = fmaf(xv, __ldg(w0r + 32 * m), ex[0]);
                ex[1] = fmaf(xv, __ldg(w1r + 32 * m), ex[1]);
                ex[2] = fmaf(xv, __ldg(w2r + 32 * m), ex[2]);
                ex[3] = fmaf(xv, __ldg(w3r + 32 * m), ex[3]);
            }
            #pragma unroll
            for (int o = 16; o; o >>= 1) {
                ex[0] += __shfl_xor_sync(FULL, ex[0], o);
                ex[1] += __shfl_xor_sync(FULL, ex[1], o);
                ex[2] += __shfl_xor_sync(FULL, ex[2], o);
                ex[3] += __shfl_xor_sync(FULL, ex[3], o);
            }
            // sort 4 candidates by (exact value desc, index asc) — replicated per lane
            int ids[4] = {cid[0], cid[1], cid[2], cid[3]};
            float vs[4] = {ex[0], ex[1], ex[2], ex[3]};
            #pragma unroll
            for (int a = 0; a < 3; a++)
                #pragma unroll
                for (int b = 0; b < 3 - a; b++) {
                    bool swap = (vs[b + 1] > vs[b]) ||
                                (vs[b + 1] == vs[b] && ids[b + 1] < ids[b]);
                    if (swap) {
                        float tv = vs[b]; vs[b] = vs[b + 1]; vs[b + 1] = tv;
                        int tii = ids[b]; ids[b] = ids[b + 1]; ids[b + 1] = tii;
                    }
                }
            bi = ids[0]; si = ids[1];
            // probs of selected experts (bf16x3 values, within tolerance)
            float q0 = __shfl_sync(FULL, p0, bi & 31);
            float q1 = __shfl_sync(FULL, p1, bi & 31);
            bvv = (bi < 32) ? q0 : q1;
            q0 = __shfl_sync(FULL, p0, si & 31);
            q1 = __shfl_sync(FULL, p1, si & 31);
            sv = (si < 32) ? q0 : q1;
        }

        float tsum = bvv + sv;
        float pn1 = bvv / tsum, pn2 = sv / tsum;

        size_t rowL = (size_t)n * E_DIM;
        out[3 * NE + rowL + lane]      = p0;
        out[3 * NE + rowL + lane + 32] = p1;
        float d0 = (lane == bi) ? pn1 : ((lane == si) ? pn2 : 0.f);
        float d1 = (lane + 32 == bi) ? pn1 : ((lane + 32 == si) ? pn2 : 0.f);
        out[rowL + lane]           = d0;
        out[rowL + lane + 32]      = d1;
        out[NE + rowL + lane]      = d0;
        out[NE + rowL + lane + 32] = d1;
        if (lane == 0) {
            size_t o5 = 4 * NE + 1 + (size_t)n * 2;
            out[o5]     = (float)bi;
            out[o5 + 1] = (float)si;
            size_t o6 = 4 * NE + 1 + (size_t)N * 2 + (size_t)n * 2;
            out[o6]     = pn1;
            out[o6 + 1] = pn2;
        }
    }

    // per-block expert prob sums + last-block aux loss
    sPart[wid * E_DIM + lane]      = auxA;
    sPart[wid * E_DIM + lane + 32] = auxB;
    __syncthreads();
    if (tid < E_DIM) {
        float ssum = 0.f;
        #pragma unroll
        for (int wd = 0; wd < 8; wd++) ssum += sPart[wd * E_DIM + tid];
        g_partials[blockIdx.x * E_DIM + tid] = ssum;
    }
    __threadfence();
    if (tid == 0) {
        unsigned int prev = atomicAdd(&g_count, 1u);
        sIsLast = (prev == (unsigned int)(gridDim.x - 1)) ? 1 : 0;
    }
    __syncthreads();

    if (sIsLast) {
        __threadfence();
        const int nBlocks = gridDim.x;
        int e = tid & 63;
        int q = tid >> 6;
        float sum = 0.f;
        for (int b = q; b < nBlocks; b += 4) sum += g_partials[b * E_DIM + e];
        sPart[q * E_DIM + e] = sum;
        __syncthreads();
        __shared__ float sq[E_DIM];
        if (tid < E_DIM) {
            float t = sPart[0 * E_DIM + tid] + sPart[1 * E_DIM + tid]
                    + sPart[2 * E_DIM + tid] + sPart[3 * E_DIM + tid];
            float m = t / (float)N;
            sq[tid] = m * m;
        }
        __syncthreads();
        if (tid == 0) {
            float a = 0.f;
            #pragma unroll
            for (int i = 0; i < E_DIM; i++) a += sq[i];
            out[4 * NE] = a;   // mean_e(E*pbar^2) = sum_e pbar^2
            g_count = 0;       // reset for graph replay
        }
    }
}

extern "C" void kernel_launch(void* const* d_in, const int* in_sizes, int n_in,
                              void* d_out, int out_size)
{
    const float* x = (const float*)d_in[0];   // [N, 2048]
    const float* w = (const float*)d_in[1];   // [64, 2048]
    float* out = (float*)d_out;

    int N = in_sizes[0] / D_DIM;              // 16384
    int nBlocks = (N + BM - 1) / BM;          // 128

    cudaFuncSetAttribute(router_gemm_kernel,
                         cudaFuncAttributeMaxDynamicSharedMemorySize, DSMEM_BYTES);

    w_split_kernel<<<(E_DIM * D_DIM + 255) / 256, 256>>>(w);
    router_gemm_kernel<<<nBlocks, NTHREADS, DSMEM_BYTES>>>(x, out, N);
    router_epilogue_kernel<<<nBlocks, NTHREADS>>>(x, w, out, N);
}

// round 11
// speedup vs baseline: 3.7610x; 1.4625x over previous
#include <cuda_runtime.h>
#include <cuda_bf16.h>
#include <math.h>
#include <stdint.h>

// Qwen2.5 MoE expert router — Round 11: 2-way bf16 rn-split, 3 HMMA products,
// 512-thread GEMM (4 warps/SMSP), separate epilogue with exact-fp32 top-4
// ordering rescue, last-block aux loss.
// out layout (fp32, reference return order):
//   [0, NE) dispatch | [NE, 2NE) combine | [2NE, 3NE) logits | [3NE, 4NE) probs
//   [4NE] aux_loss | [4NE+1, +2N) top_k_idx (float) | next 2N: top_k_probs_norm

#define D_DIM 2048
#define E_DIM 64
#define BM 128
#define NKT (D_DIM / 64)       // 32 k-tiles of 64
#define NTH_G 512
#define NTH_E 256
#define BM_E 64
#define GAP_TH 1e-4f

#define ROW_BYTES 144          // 128B data + 16B pad: ldmatrix & STS conflict-free
#define SA_OFF(s) ((s) * (BM * ROW_BYTES))                    // 2 x 18432
#define SB_OFF(s) (2 * BM * ROW_BYTES + (s) * (E_DIM * ROW_BYTES)) // 2 x 9216
#define DSMEM_BYTES (2 * BM * ROW_BYTES + 2 * E_DIM * ROW_BYTES)   // 55296

__device__ __forceinline__ uint32_t smem_u32(const void* p) {
    uint32_t a;
    asm("{ .reg .u64 t; cvta.to.shared.u64 t, %1; cvt.u32.u64 %0, t; }" : "=r"(a) : "l"(p));
    return a;
}
__device__ __forceinline__ void ldsm_x4(uint32_t* r, uint32_t addr) {
    asm volatile("ldmatrix.sync.aligned.m8n8.x4.shared.b16 {%0,%1,%2,%3}, [%4];"
                 : "=r"(r[0]), "=r"(r[1]), "=r"(r[2]), "=r"(r[3]) : "r"(addr));
}
__device__ __forceinline__ void mma_bf16(float* d, const uint32_t* a,
                                         uint32_t b0, uint32_t b1) {
    asm volatile("mma.sync.aligned.m16n8k16.row.col.f32.bf16.bf16.f32 "
                 "{%0,%1,%2,%3}, {%4,%5,%6,%7}, {%8,%9}, {%0,%1,%2,%3};"
                 : "+f"(d[0]), "+f"(d[1]), "+f"(d[2]), "+f"(d[3])
                 : "r"(a[0]), "r"(a[1]), "r"(a[2]), "r"(a[3]), "r"(b0), "r"(b1));
}
__device__ __forceinline__ uint32_t pack_bf16x2(float lo, float hi) {
    uint32_t r;
    asm("cvt.rn.bf16x2.f32 %0, %1, %2;" : "=r"(r) : "f"(hi), "f"(lo));
    return r;
}

__device__ __align__(16) __nv_bfloat16 g_w0[E_DIM * D_DIM];
__device__ __align__(16) __nv_bfloat16 g_w1[E_DIM * D_DIM];
__device__ float g_partials[256 * E_DIM];
__device__ unsigned int g_count = 0;

__global__ void w_split_kernel(const float* __restrict__ w) {
    int i = blockIdx.x * blockDim.x + threadIdx.x;
    if (i < E_DIM * D_DIM) {
        float f = w[i];
        __nv_bfloat16 h = __float2bfloat16_rn(f);
        float back = __uint_as_float((uint32_t)__bfloat16_as_ushort(h) << 16);
        g_w0[i] = h;
        g_w1[i] = __float2bfloat16_rn(f - back);   // f-back exact in fp32
    }
}

// ================= Kernel 1: GEMM (logits only) =================
// 16 warps: mw = wid&3 (M: 32 rows), nw = wid>>2 (N: 16 cols).
__global__ __launch_bounds__(NTH_G, 1)
void router_gemm_kernel(const float* __restrict__ x,
                        float* __restrict__ out,
                        int N)
{
    extern __shared__ char dsmem[];
    const uint32_t smem_b = smem_u32(dsmem);
    const int tid = threadIdx.x;
    const int wid = tid >> 5;
    const int lane = tid & 31;
    const int n0 = blockIdx.x * BM;

    const int mw = wid & 3;
    const int nw = wid >> 2;

    const uint32_t aRowLo = (uint32_t)((mw * 32 + (lane & 15)) * ROW_BYTES
                                       + (lane >> 4) * 16);
    const uint32_t aRowHi = aRowLo + 16 * ROW_BYTES;
    const uint32_t bOff = (uint32_t)((nw * 16 + ((lane >> 4) & 1) * 8 + (lane & 7)) * ROW_BYTES
                                     + ((lane >> 3) & 1) * 16);

    // staging: A 2048 float4/tile -> 4/thread; B 512 uint4/split -> 1/thread
    float4 v[4];
    uint4 bq0, bq1;

    float accM[2][2][4];   // product x0*w0
    float accS[2][2][4];   // products x0*w1 + x1*w0
    #pragma unroll
    for (int i = 0; i < 2; i++)
        #pragma unroll
        for (int j = 0; j < 2; j++)
            #pragma unroll
            for (int q = 0; q < 4; q++) { accM[i][j][q] = 0.f; accS[i][j][q] = 0.f; }

    const uint4* __restrict__ w0v = reinterpret_cast<const uint4*>(g_w0);
    const uint4* __restrict__ w1v = reinterpret_cast<const uint4*>(g_w1);

    const int er = tid >> 3, c16 = tid & 7;   // B staging coords

    // prologue: stage tile 0
    #pragma unroll
    for (int p = 0; p < 4; p++) {
        int idx = tid + NTH_G * p;
        int row = idx >> 4, c4 = idx & 15;
        int n = n0 + row; if (n > N - 1) n = N - 1;
        v[p] = *reinterpret_cast<const float4*>(x + (size_t)n * D_DIM + c4 * 4);
    }
    {
        int gi = er * (D_DIM / 8) + c16;
        bq0 = w0v[gi]; bq1 = w1v[gi];
    }

    for (int kt = 0; kt < NKT; kt++) {
        __syncthreads();

        // convert + store A (2-way rn split)
        char* sA0 = dsmem + SA_OFF(0);
        char* sA1 = dsmem + SA_OFF(1);
        #pragma unroll
        for (int p = 0; p < 4; p++) {
            int idx = tid + NTH_G * p;
            int row = idx >> 4, c4 = idx & 15;
            float4 f = v[p];
            __nv_bfloat16 h0 = __float2bfloat16_rn(f.x);
            __nv_bfloat16 h1 = __float2bfloat16_rn(f.y);
            __nv_bfloat16 h2 = __float2bfloat16_rn(f.z);
            __nv_bfloat16 h3 = __float2bfloat16_rn(f.w);
            uint32_t u0 = __bfloat16_as_ushort(h0), u1 = __bfloat16_as_ushort(h1);
            uint32_t u2 = __bfloat16_as_ushort(h2), u3 = __bfloat16_as_ushort(h3);
            float r0 = f.x - __uint_as_float(u0 << 16);
            float r1 = f.y - __uint_as_float(u1 << 16);
            float r2 = f.z - __uint_as_float(u2 << 16);
            float r3 = f.w - __uint_as_float(u3 << 16);
            uint32_t hiA = u0 | (u1 << 16);
            uint32_t hiB = u2 | (u3 << 16);
            uint32_t loA = pack_bf16x2(r0, r1);
            uint32_t loB = pack_bf16x2(r2, r3);
            uint32_t off = (uint32_t)(row * ROW_BYTES + c4 * 8);
            *reinterpret_cast<uint2*>(sA0 + off) = make_uint2(hiA, hiB);
            *reinterpret_cast<uint2*>(sA1 + off) = make_uint2(loA, loB);
        }
        // store B
        {
            uint32_t off = (uint32_t)(er * ROW_BYTES + c16 * 16);
            *reinterpret_cast<uint4*>(dsmem + SB_OFF(0) + off) = bq0;
            *reinterpret_cast<uint4*>(dsmem + SB_OFF(1) + off) = bq1;
        }
        __syncthreads();

        // prefetch next tile
        if (kt + 1 < NKT) {
            const int kbase = (kt + 1) * 64;
            #pragma unroll
            for (int p = 0; p < 4; p++) {
                int idx = tid + NTH_G * p;
                int row = idx >> 4, c4 = idx & 15;
                int n = n0 + row; if (n > N - 1) n = N - 1;
                v[p] = *reinterpret_cast<const float4*>(x + (size_t)n * D_DIM + kbase + c4 * 4);
            }
            int gi = er * (D_DIM / 8) + (kt + 1) * 8 + c16;
            bq0 = w0v[gi]; bq1 = w1v[gi];
        }

        // compute: 3 products x 4 k16-steps
        const uint32_t a0l = smem_b + SA_OFF(0) + aRowLo;
        const uint32_t a0h = smem_b + SA_OFF(0) + aRowHi;
        const uint32_t a1l = smem_b + SA_OFF(1) + aRowLo;
        const uint32_t a1h = smem_b + SA_OFF(1) + aRowHi;
        const uint32_t b0a = smem_b + SB_OFF(0) + bOff;
        const uint32_t b1a = smem_b + SB_OFF(1) + bOff;

        #pragma unroll
        for (int j = 0; j < 4; j++) {
            uint32_t fa0l[4], fa0h[4], fa1l[4], fa1h[4], fb0[4], fb1[4];
            ldsm_x4(fa0l, a0l + j * 32);
            ldsm_x4(fa0h, a0h + j * 32);
            ldsm_x4(fa1l, a1l + j * 32);
            ldsm_x4(fa1h, a1h + j * 32);
            ldsm_x4(fb0, b0a + j * 32);
            ldsm_x4(fb1, b1a + j * 32);
            // p0 = x0*w0 -> accM
            mma_bf16(accM[0][0], fa0l, fb0[0], fb0[1]);
            mma_bf16(accM[0][1], fa0l, fb0[2], fb0[3]);
            mma_bf16(accM[1][0], fa0h, fb0[0], fb0[1]);
            mma_bf16(accM[1][1], fa0h, fb0[2], fb0[3]);
            // p1 = x0*w1 -> accS
            mma_bf16(accS[0][0], fa0l, fb1[0], fb1[1]);
            mma_bf16(accS[0][1], fa0l, fb1[2], fb1[3]);
            mma_bf16(accS[1][0], fa0h, fb1[0], fb1[1]);
            mma_bf16(accS[1][1], fa0h, fb1[2], fb1[3]);
            // p2 = x1*w0 -> accS
            mma_bf16(accS[0][0], fa1l, fb0[0], fb0[1]);
            mma_bf16(accS[0][1], fa1l, fb0[2], fb0[3]);
            mma_bf16(accS[1][0], fa1h, fb0[0], fb0[1]);
            mma_bf16(accS[1][1], fa1h, fb0[2], fb0[3]);
        }
    }

    // write logits: out[2NE + n*64 + c]
    const size_t NE = (size_t)N * E_DIM;
    float* Lout = out + 2 * NE;
    #pragma unroll
    for (int mh = 0; mh < 2; mh++)
        #pragma unroll
        for (int nh = 0; nh < 2; nh++) {
            int r = n0 + mw * 32 + 16 * mh + (lane >> 2);
            int c = nw * 16 + 8 * nh + 2 * (lane & 3);
            float v0 = accM[mh][nh][0] + accS[mh][nh][0];
            float v1 = accM[mh][nh][1] + accS[mh][nh][1];
            float v2 = accM[mh][nh][2] + accS[mh][nh][2];
            float v3 = accM[mh][nh][3] + accS[mh][nh][3];
            *reinterpret_cast<float2*>(Lout + (size_t)r * E_DIM + c) = make_float2(v0, v1);
            *reinterpret_cast<float2*>(Lout + (size_t)(r + 8) * E_DIM + c) = make_float2(v2, v3);
        }
}

// ================= Kernel 2: epilogue =================
__global__ __launch_bounds__(NTH_E)
void router_epilogue_kernel(const float* __restrict__ x,
                            const float* __restrict__ w,
                            float* __restrict__ out,
                            int N)
{
    __shared__ float sPart[8 * E_DIM];
    __shared__ float sq[E_DIM];
    __shared__ int sIsLast;

    const int tid = threadIdx.x;
    const int wid = tid >> 5;
    const int lane = tid & 31;
    const int n0 = blockIdx.x * BM_E;
    const size_t NE = (size_t)N * E_DIM;
    const float* __restrict__ Lin = out + 2 * NE;
    const float NEG_INF = __int_as_float(0xff800000);
    const unsigned FULL = 0xffffffffu;

    float auxA = 0.f, auxB = 0.f;

    for (int tk = wid; tk < BM_E; tk += 8) {
        int n = n0 + tk;
        if (n >= N) continue;  // warp-uniform

        float v0 = Lin[(size_t)n * E_DIM + lane];
        float v1 = Lin[(size_t)n * E_DIM + lane + 32];

        float mx = fmaxf(v0, v1);
        #pragma unroll
        for (int o = 16; o; o >>= 1) mx = fmaxf(mx, __shfl_xor_sync(FULL, mx, o));
        float x0 = expf(v0 - mx), x1 = expf(v1 - mx);
        float s = x0 + x1;
        #pragma unroll
        for (int o = 16; o; o >>= 1) s += __shfl_xor_sync(FULL, s, o);
        float p0 = x0 / s, p1 = x1 / s;
        auxA += p0; auxB += p1;

        // ranks 1..4 (value desc, index asc on ties)
        int cid[4]; float cv[4];
        float m0v = p0, m1v = p1;
        #pragma unroll
        for (int rko = 0; rko < 4; rko++) {
            float bv; int bix;
            if (m0v >= m1v) { bv = m0v; bix = lane; } else { bv = m1v; bix = lane + 32; }
            #pragma unroll
            for (int o = 16; o; o >>= 1) {
                float ov = __shfl_xor_sync(FULL, bv, o);
                int   oi = __shfl_xor_sync(FULL, bix, o);
                if (ov > bv || (ov == bv && oi < bix)) { bv = ov; bix = oi; }
            }
            cv[rko] = bv; cid[rko] = bix;
            if (lane == bix) m0v = NEG_INF;
            if (lane + 32 == bix) m1v = NEG_INF;
        }

        int bi = cid[0], si = cid[1];
        float bvv = cv[0], sv = cv[1];

        // exact fp32 ordering of top-4 when margins tight (warp-uniform)
        if (cv[0] - cv[1] < GAP_TH || cv[1] - cv[2] < GAP_TH || cv[2] - cv[3] < GAP_TH) {
            float ex[4] = {0.f, 0.f, 0.f, 0.f};
            const float* xr = x + (size_t)n * D_DIM + lane;
            const float* w0r = w + (size_t)cid[0] * D_DIM + lane;
            const float* w1r = w + (size_t)cid[1] * D_DIM + lane;
            const float* w2r = w + (size_t)cid[2] * D_DIM + lane;
            const float* w3r = w + (size_t)cid[3] * D_DIM + lane;
            #pragma unroll 4
            for (int m = 0; m < D_DIM / 32; m++) {
                float xv = __ldg(xr + 32 * m);
                ex[0] = fmaf(xv, __ldg(w0r + 32 * m), ex[0]);
                ex[1] = fmaf(xv, __ldg(w1r + 32 * m), ex[1]);
                ex[2] = fmaf(xv, __ldg(w2r + 32 * m), ex[2]);
                ex[3] = fmaf(xv, __ldg(w3r + 32 * m), ex[3]);
            }
            #pragma unroll
            for (int o = 16; o; o >>= 1) {
                ex[0] += __shfl_xor_sync(FULL, ex[0], o);
                ex[1] += __shfl_xor_sync(FULL, ex[1], o);
                ex[2] += __shfl_xor_sync(FULL, ex[2], o);
                ex[3] += __shfl_xor_sync(FULL, ex[3], o);
            }
            int ids[4] = {cid[0], cid[1], cid[2], cid[3]};
            float vs[4] = {ex[0], ex[1], ex[2], ex[3]};
            #pragma unroll
            for (int a = 0; a < 3; a++)
                #pragma unroll
                for (int b = 0; b < 3 - a; b++) {
                    bool sw = (vs[b + 1] > vs[b]) ||
                              (vs[b + 1] == vs[b] && ids[b + 1] < ids[b]);
                    if (sw) {
                        float tv = vs[b]; vs[b] = vs[b + 1]; vs[b + 1] = tv;
                        int ti = ids[b]; ids[b] = ids[b + 1]; ids[b + 1] = ti;
                    }
                }
            bi = ids[0]; si = ids[1];
            float q0 = __shfl_sync(FULL, p0, bi & 31);
            float q1 = __shfl_sync(FULL, p1, bi & 31);
            bvv = (bi < 32) ? q0 : q1;
            q0 = __shfl_sync(FULL, p0, si & 31);
            q1 = __shfl_sync(FULL, p1, si & 31);
            sv = (si < 32) ? q0 : q1;
        }

        float tsum = bvv + sv;
        float pn1 = bvv / tsum, pn2 = sv / tsum;

        size_t rowL = (size_t)n * E_DIM;
        out[3 * NE + rowL + lane]      = p0;
        out[3 * NE + rowL + lane + 32] = p1;
        float d0 = (lane == bi) ? pn1 : ((lane == si) ? pn2 : 0.f);
        float d1 = (lane + 32 == bi) ? pn1 : ((lane + 32 == si) ? pn2 : 0.f);
        out[rowL + lane]           = d0;
        out[rowL + lane + 32]      = d1;
        out[NE + rowL + lane]      = d0;
        out[NE + rowL + lane + 32] = d1;
        if (lane == 0) {
            size_t o5 = 4 * NE + 1 + (size_t)n * 2;
            out[o5]     = (float)bi;
            out[o5 + 1] = (float)si;
            size_t o6 = 4 * NE + 1 + (size_t)N * 2 + (size_t)n * 2;
            out[o6]     = pn1;
            out[o6 + 1] = pn2;
        }
    }

    sPart[wid * E_DIM + lane]      = auxA;
    sPart[wid * E_DIM + lane + 32] = auxB;
    __syncthreads();
    if (tid < E_DIM) {
        float ssum = 0.f;
        #pragma unroll
        for (int wd = 0; wd < 8; wd++) ssum += sPart[wd * E_DIM + tid];
        g_partials[blockIdx.x * E_DIM + tid] = ssum;
    }
    __threadfence();
    if (tid == 0) {
        unsigned int prev = atomicAdd(&g_count, 1u);
        sIsLast = (prev == (unsigned int)(gridDim.x - 1)) ? 1 : 0;
    }
    __syncthreads();

    if (sIsLast) {
        __threadfence();
        const int nBlocks = gridDim.x;
        int e = tid & 63;
        int q = tid >> 6;
        float sum = 0.f;
        for (int b = q; b < nBlocks; b += 4) sum += g_partials[b * E_DIM + e];
        sPart[q * E_DIM + e] = sum;
        __syncthreads();
        if (tid < E_DIM) {
            float t = sPart[0 * E_DIM + tid] + sPart[1 * E_DIM + tid]
                    + sPart[2 * E_DIM + tid] + sPart[3 * E_DIM + tid];
            float m = t / (float)N;
            sq[tid] = m * m;
        }
        __syncthreads();
        if (tid == 0) {
            float a = 0.f;
            #pragma unroll
            for (int i = 0; i < E_DIM; i++) a += sq[i];
            out[4 * NE] = a;   // mean_e(E*pbar^2) = sum_e pbar^2
            g_count = 0;       // reset for graph replay
        }
    }
}

extern "C" void kernel_launch(void* const* d_in, const int* in_sizes, int n_in,
                              void* d_out, int out_size)
{
    const float* x = (const float*)d_in[0];   // [N, 2048]
    const float* w = (const float*)d_in[1];   // [64, 2048]
    float* out = (float*)d_out;

    int N = in_sizes[0] / D_DIM;              // 16384
    int nBlkG = (N + BM - 1) / BM;            // 128
    int nBlkE = (N + BM_E - 1) / BM_E;        // 256

    cudaFuncSetAttribute(router_gemm_kernel,
                         cudaFuncAttributeMaxDynamicSharedMemorySize, DSMEM_BYTES);

    w_split_kernel<<<(E_DIM * D_DIM + 255) / 256, 256>>>(w);
    router_gemm_kernel<<<nBlkG, NTH_G, DSMEM_BYTES>>>(x, out, N);
    router_epilogue_kernel<<<nBlkE, NTH_E>>>(x, w, out, N);
}

// round 12
// speedup vs baseline: 5.0361x; 1.3390x over previous
#include <cuda_runtime.h>
#include <cuda_fp16.h>
#include <math.h>
#include <stdint.h>

// Qwen2.5 MoE expert router — Round 12: SINGLE-product fp16 HMMA GEMM
// (logit err ~1.8e-4 abs, within 1e-3 rel threshold), separate epilogue with
// exact-fp32 top-6 ordering rescue, last-block aux loss.
// out layout (fp32, reference return order):
//   [0, NE) dispatch | [NE, 2NE) combine | [2NE, 3NE) logits | [3NE, 4NE) probs
//   [4NE] aux_loss | [4NE+1, +2N) top_k_idx (float) | next 2N: top_k_probs_norm

#define D_DIM 2048
#define E_DIM 64
#define BM 128
#define NKT (D_DIM / 64)       // 32 k-tiles of 64
#define NTH_G 512
#define NTH_E 256
#define BM_E 64
#define GAP_TH 2e-4f
#define NCAND 6

#define ROW_BYTES 144          // 128B data + 16B pad: ldmatrix & STS conflict-free
#define SB_OFF (BM * ROW_BYTES)                    // 18432
#define DSMEM_BYTES (BM * ROW_BYTES + E_DIM * ROW_BYTES)   // 27648

__device__ __forceinline__ uint32_t smem_u32(const void* p) {
    uint32_t a;
    asm("{ .reg .u64 t; cvta.to.shared.u64 t, %1; cvt.u32.u64 %0, t; }" : "=r"(a) : "l"(p));
    return a;
}
__device__ __forceinline__ void ldsm_x4(uint32_t* r, uint32_t addr) {
    asm volatile("ldmatrix.sync.aligned.m8n8.x4.shared.b16 {%0,%1,%2,%3}, [%4];"
                 : "=r"(r[0]), "=r"(r[1]), "=r"(r[2]), "=r"(r[3]) : "r"(addr));
}
__device__ __forceinline__ void mma_f16(float* d, const uint32_t* a,
                                        uint32_t b0, uint32_t b1) {
    asm volatile("mma.sync.aligned.m16n8k16.row.col.f32.f16.f16.f32 "
                 "{%0,%1,%2,%3}, {%4,%5,%6,%7}, {%8,%9}, {%0,%1,%2,%3};"
                 : "+f"(d[0]), "+f"(d[1]), "+f"(d[2]), "+f"(d[3])
                 : "r"(a[0]), "r"(a[1]), "r"(a[2]), "r"(a[3]), "r"(b0), "r"(b1));
}

__device__ __align__(16) __half g_wh[E_DIM * D_DIM];
__device__ float g_partials[256 * E_DIM];
__device__ unsigned int g_count = 0;

__global__ void w_half_kernel(const float* __restrict__ w) {
    int i = blockIdx.x * blockDim.x + threadIdx.x;
    if (i < E_DIM * D_DIM) g_wh[i] = __float2half_rn(w[i]);
}

// ================= Kernel 1: GEMM (logits only) =================
// 16 warps: mw = wid&3 (M: 32 rows), nw = wid>>2 (N: 16 cols).
__global__ __launch_bounds__(NTH_G, 1)
void router_gemm_kernel(const float* __restrict__ x,
                        float* __restrict__ out,
                        int N)
{
    extern __shared__ char dsmem[];
    const uint32_t smem_b = smem_u32(dsmem);
    const int tid = threadIdx.x;
    const int wid = tid >> 5;
    const int lane = tid & 31;
    const int n0 = blockIdx.x * BM;

    const int mw = wid & 3;
    const int nw = wid >> 2;

    const uint32_t aRowLo = (uint32_t)((mw * 32 + (lane & 15)) * ROW_BYTES
                                       + (lane >> 4) * 16);
    const uint32_t aRowHi = aRowLo + 16 * ROW_BYTES;
    const uint32_t bOff = (uint32_t)((nw * 16 + ((lane >> 4) & 1) * 8 + (lane & 7)) * ROW_BYTES
                                     + ((lane >> 3) & 1) * 16);

    float4 v[4];          // A staging: 2048 float4/tile -> 4/thread
    uint4 bq;             // B staging: 512 uint4/tile -> 1/thread

    float acc[2][2][4];
    #pragma unroll
    for (int i = 0; i < 2; i++)
        #pragma unroll
        for (int j = 0; j < 2; j++)
            #pragma unroll
            for (int q = 0; q < 4; q++) acc[i][j][q] = 0.f;

    const uint4* __restrict__ whv = reinterpret_cast<const uint4*>(g_wh);
    const int er = tid >> 3, c16 = tid & 7;   // B staging coords

    // prologue: stage tile 0
    #pragma unroll
    for (int p = 0; p < 4; p++) {
        int idx = tid + NTH_G * p;
        int row = idx >> 4, c4 = idx & 15;
        int n = n0 + row; if (n > N - 1) n = N - 1;
        v[p] = *reinterpret_cast<const float4*>(x + (size_t)n * D_DIM + c4 * 4);
    }
    bq = whv[er * (D_DIM / 8) + c16];

    for (int kt = 0; kt < NKT; kt++) {
        __syncthreads();

        // convert fp32 -> fp16 and store A; store B
        #pragma unroll
        for (int p = 0; p < 4; p++) {
            int idx = tid + NTH_G * p;
            int row = idx >> 4, c4 = idx & 15;
            float4 f = v[p];
            __half2 h01 = __floats2half2_rn(f.x, f.y);
            __half2 h23 = __floats2half2_rn(f.z, f.w);
            uint32_t u01 = *reinterpret_cast<uint32_t*>(&h01);
            uint32_t u23 = *reinterpret_cast<uint32_t*>(&h23);
            uint32_t off = (uint32_t)(row * ROW_BYTES + c4 * 8);
            *reinterpret_cast<uint2*>(dsmem + off) = make_uint2(u01, u23);
        }
        {
            uint32_t off = (uint32_t)(er * ROW_BYTES + c16 * 16);
            *reinterpret_cast<uint4*>(dsmem + SB_OFF + off) = bq;
        }
        __syncthreads();

        // prefetch next tile
        if (kt + 1 < NKT) {
            const int kbase = (kt + 1) * 64;
            #pragma unroll
            for (int p = 0; p < 4; p++) {
                int idx = tid + NTH_G * p;
                int row = idx >> 4, c4 = idx & 15;
                int n = n0 + row; if (n > N - 1) n = N - 1;
                v[p] = *reinterpret_cast<const float4*>(x + (size_t)n * D_DIM + kbase + c4 * 4);
            }
            bq = whv[er * (D_DIM / 8) + (kt + 1) * 8 + c16];
        }

        // compute: 1 product x 4 k16-steps
        const uint32_t aLo = smem_b + aRowLo;
        const uint32_t aHi = smem_b + aRowHi;
        const uint32_t bAd = smem_b + SB_OFF + bOff;

        #pragma unroll
        for (int j = 0; j < 4; j++) {
            uint32_t faL[4], faH[4], fb[4];
            ldsm_x4(faL, aLo + j * 32);
            ldsm_x4(faH, aHi + j * 32);
            ldsm_x4(fb, bAd + j * 32);
            mma_f16(acc[0][0], faL, fb[0], fb[1]);
            mma_f16(acc[0][1], faL, fb[2], fb[3]);
            mma_f16(acc[1][0], faH, fb[0], fb[1]);
            mma_f16(acc[1][1], faH, fb[2], fb[3]);
        }
    }

    // write logits: out[2NE + n*64 + c]
    const size_t NE = (size_t)N * E_DIM;
    float* Lout = out + 2 * NE;
    #pragma unroll
    for (int mh = 0; mh < 2; mh++)
        #pragma unroll
        for (int nh = 0; nh < 2; nh++) {
            int r = n0 + mw * 32 + 16 * mh + (lane >> 2);
            int c = nw * 16 + 8 * nh + 2 * (lane & 3);
            *reinterpret_cast<float2*>(Lout + (size_t)r * E_DIM + c) =
                make_float2(acc[mh][nh][0], acc[mh][nh][1]);
            *reinterpret_cast<float2*>(Lout + (size_t)(r + 8) * E_DIM + c) =
                make_float2(acc[mh][nh][2], acc[mh][nh][3]);
        }
}

// ================= Kernel 2: epilogue =================
__global__ __launch_bounds__(NTH_E)
void router_epilogue_kernel(const float* __restrict__ x,
                            const float* __restrict__ w,
                            float* __restrict__ out,
                            int N)
{
    __shared__ float sPart[8 * E_DIM];
    __shared__ float sq[E_DIM];
    __shared__ int sIsLast;

    const int tid = threadIdx.x;
    const int wid = tid >> 5;
    const int lane = tid & 31;
    const int n0 = blockIdx.x * BM_E;
    const size_t NE = (size_t)N * E_DIM;
    const float* __restrict__ Lin = out + 2 * NE;
    const float NEG_INF = __int_as_float(0xff800000);
    const unsigned FULL = 0xffffffffu;

    float auxA = 0.f, auxB = 0.f;

    for (int tk = wid; tk < BM_E; tk += 8) {
        int n = n0 + tk;
        if (n >= N) continue;  // warp-uniform

        float v0 = Lin[(size_t)n * E_DIM + lane];
        float v1 = Lin[(size_t)n * E_DIM + lane + 32];

        float mx = fmaxf(v0, v1);
        #pragma unroll
        for (int o = 16; o; o >>= 1) mx = fmaxf(mx, __shfl_xor_sync(FULL, mx, o));
        float x0 = expf(v0 - mx), x1 = expf(v1 - mx);
        float s = x0 + x1;
        #pragma unroll
        for (int o = 16; o; o >>= 1) s += __shfl_xor_sync(FULL, s, o);
        float p0 = x0 / s, p1 = x1 / s;
        auxA += p0; auxB += p1;

        // ranks 1..NCAND (value desc, index asc on ties)
        int cid[NCAND]; float cv[NCAND];
        float m0v = p0, m1v = p1;
        #pragma unroll
        for (int rko = 0; rko < NCAND; rko++) {
            float bv; int bix;
            if (m0v >= m1v) { bv = m0v; bix = lane; } else { bv = m1v; bix = lane + 32; }
            #pragma unroll
            for (int o = 16; o; o >>= 1) {
                float ov = __shfl_xor_sync(FULL, bv, o);
                int   oi = __shfl_xor_sync(FULL, bix, o);
                if (ov > bv || (ov == bv && oi < bix)) { bv = ov; bix = oi; }
            }
            cv[rko] = bv; cid[rko] = bix;
            if (lane == bix) m0v = NEG_INF;
            if (lane + 32 == bix) m1v = NEG_INF;
        }

        int bi = cid[0], si = cid[1];
        float bvv = cv[0], sv = cv[1];

        // exact fp32 ordering of top-NCAND when margins tight (warp-uniform)
        if (cv[0] - cv[1] < GAP_TH || cv[1] - cv[2] < GAP_TH) {
            float ex[NCAND];
            #pragma unroll
            for (int q = 0; q < NCAND; q++) ex[q] = 0.f;
            const float* xr = x + (size_t)n * D_DIM + lane;
            const float* wr[NCAND];
            #pragma unroll
            for (int q = 0; q < NCAND; q++)
                wr[q] = w + (size_t)cid[q] * D_DIM + lane;
            #pragma unroll 4
            for (int m = 0; m < D_DIM / 32; m++) {
                float xv = __ldg(xr + 32 * m);
                #pragma unroll
                for (int q = 0; q < NCAND; q++)
                    ex[q] = fmaf(xv, __ldg(wr[q] + 32 * m), ex[q]);
            }
            #pragma unroll
            for (int o = 16; o; o >>= 1)
                #pragma unroll
                for (int q = 0; q < NCAND; q++)
                    ex[q] += __shfl_xor_sync(FULL, ex[q], o);
            // sort NCAND by (exact value desc, index asc) — replicated per lane
            int ids[NCAND]; float vs[NCAND];
            #pragma unroll
            for (int q = 0; q < NCAND; q++) { ids[q] = cid[q]; vs[q] = ex[q]; }
            #pragma unroll
            for (int a = 0; a < NCAND - 1; a++)
                #pragma unroll
                for (int b = 0; b < NCAND - 1 - a; b++) {
                    bool sw = (vs[b + 1] > vs[b]) ||
                              (vs[b + 1] == vs[b] && ids[b + 1] < ids[b]);
                    if (sw) {
                        float tv = vs[b]; vs[b] = vs[b + 1]; vs[b + 1] = tv;
                        int ti = ids[b]; ids[b] = ids[b + 1]; ids[b + 1] = ti;
                    }
                }
            bi = ids[0]; si = ids[1];
            float q0 = __shfl_sync(FULL, p0, bi & 31);
            float q1 = __shfl_sync(FULL, p1, bi & 31);
            bvv = (bi < 32) ? q0 : q1;
            q0 = __shfl_sync(FULL, p0, si & 31);
            q1 = __shfl_sync(FULL, p1, si & 31);
            sv = (si < 32) ? q0 : q1;
        }

        float tsum = bvv + sv;
        float pn1 = bvv / tsum, pn2 = sv / tsum;

        size_t rowL = (size_t)n * E_DIM;
        out[3 * NE + rowL + lane]      = p0;
        out[3 * NE + rowL + lane + 32] = p1;
        float d0 = (lane == bi) ? pn1 : ((lane == si) ? pn2 : 0.f);
        float d1 = (lane + 32 == bi) ? pn1 : ((lane + 32 == si) ? pn2 : 0.f);
        out[rowL + lane]           = d0;
        out[rowL + lane + 32]      = d1;
        out[NE + rowL + lane]      = d0;
        out[NE + rowL + lane + 32] = d1;
        if (lane == 0) {
            size_t o5 = 4 * NE + 1 + (size_t)n * 2;
            out[o5]     = (float)bi;
            out[o5 + 1] = (float)si;
            size_t o6 = 4 * NE + 1 + (size_t)N * 2 + (size_t)n * 2;
            out[o6]     = pn1;
            out[o6 + 1] = pn2;
        }
    }

    sPart[wid * E_DIM + lane]      = auxA;
    sPart[wid * E_DIM + lane + 32] = auxB;
    __syncthreads();
    if (tid < E_DIM) {
        float ssum = 0.f;
        #pragma unroll
        for (int wd = 0; wd < 8; wd++) ssum += sPart[wd * E_DIM + tid];
        g_partials[blockIdx.x * E_DIM + tid] = ssum;
    }
    __threadfence();
    if (tid == 0) {
        unsigned int prev = atomicAdd(&g_count, 1u);
        sIsLast = (prev == (unsigned int)(gridDim.x - 1)) ? 1 : 0;
    }
    __syncthreads();

    if (sIsLast) {
        __threadfence();
        const int nBlocks = gridDim.x;
        int e = tid & 63;
        int q = tid >> 6;
        float sum = 0.f;
        for (int b = q; b < nBlocks; b += 4) sum += g_partials[b * E_DIM + e];
        sPart[q * E_DIM + e] = sum;
        __syncthreads();
        if (tid < E_DIM) {
            float t = sPart[0 * E_DIM + tid] + sPart[1 * E_DIM + tid]
                    + sPart[2 * E_DIM + tid] + sPart[3 * E_DIM + tid];
            float m = t / (float)N;
            sq[tid] = m * m;
        }
        __syncthreads();
        if (tid == 0) {
            float a = 0.f;
            #pragma unroll
            for (int i = 0; i < E_DIM; i++) a += sq[i];
            out[4 * NE] = a;   // mean_e(E*pbar^2) = sum_e pbar^2
            g_count = 0;       // reset for graph replay
        }
    }
}

extern "C" void kernel_launch(void* const* d_in, const int* in_sizes, int n_in,
                              void* d_out, int out_size)
{
    const float* x = (const float*)d_in[0];   // [N, 2048]
    const float* w = (const float*)d_in[1];   // [64, 2048]
    float* out = (float*)d_out;

    int N = in_sizes[0] / D_DIM;              // 16384
    int nBlkG = (N + BM - 1) / BM;            // 128
    int nBlkE = (N + BM_E - 1) / BM_E;        // 256

    cudaFuncSetAttribute(router_gemm_kernel,
                         cudaFuncAttributeMaxDynamicSharedMemorySize, DSMEM_BYTES);

    w_half_kernel<<<(E_DIM * D_DIM + 255) / 256, 256>>>(w);
    router_gemm_kernel<<<nBlkG, NTH_G, DSMEM_BYTES>>>(x, out, N);
    router_epilogue_kernel<<<nBlkE, NTH_E>>>(x, w, out, N);
}

// round 13
// speedup vs baseline: 5.5601x; 1.1041x over previous
#include <cuda_runtime.h>
#include <cuda_fp16.h>
#include <math.h>
#include <stdint.h>

// Qwen2.5 MoE expert router — Round 13: fp16 HMMA GEMM with fused w-conversion,
// lean epilogue (3-rank common case, lazy top-6 exact-fp32 rescue, 512 blocks),
// last-block aux loss.
// out layout (fp32, reference return order):
//   [0, NE) dispatch | [NE, 2NE) combine | [2NE, 3NE) logits | [3NE, 4NE) probs
//   [4NE] aux_loss | [4NE+1, +2N) top_k_idx (float) | next 2N: top_k_probs_norm

#define D_DIM 2048
#define E_DIM 64
#define BM 128
#define NKT (D_DIM / 64)       // 32 k-tiles of 64
#define NTH_G 512
#define NTH_E 256
#define BM_E 32
#define GAP_TH 2e-4f
#define NCAND 6

#define ROW_BYTES 144          // 128B data + 16B pad: ldmatrix & STS conflict-free
#define SB_OFF (BM * ROW_BYTES)                            // 18432
#define DSMEM_BYTES (BM * ROW_BYTES + E_DIM * ROW_BYTES)   // 27648

__device__ __forceinline__ uint32_t smem_u32(const void* p) {
    uint32_t a;
    asm("{ .reg .u64 t; cvta.to.shared.u64 t, %1; cvt.u32.u64 %0, t; }" : "=r"(a) : "l"(p));
    return a;
}
__device__ __forceinline__ void ldsm_x4(uint32_t* r, uint32_t addr) {
    asm volatile("ldmatrix.sync.aligned.m8n8.x4.shared.b16 {%0,%1,%2,%3}, [%4];"
                 : "=r"(r[0]), "=r"(r[1]), "=r"(r[2]), "=r"(r[3]) : "r"(addr));
}
__device__ __forceinline__ void mma_f16(float* d, const uint32_t* a,
                                        uint32_t b0, uint32_t b1) {
    asm volatile("mma.sync.aligned.m16n8k16.row.col.f32.f16.f16.f32 "
                 "{%0,%1,%2,%3}, {%4,%5,%6,%7}, {%8,%9}, {%0,%1,%2,%3};"
                 : "+f"(d[0]), "+f"(d[1]), "+f"(d[2]), "+f"(d[3])
                 : "r"(a[0]), "r"(a[1]), "r"(a[2]), "r"(a[3]), "r"(b0), "r"(b1));
}
__device__ __forceinline__ uint32_t pack_half2(float lo, float hi) {
    __half2 h = __floats2half2_rn(lo, hi);
    return *reinterpret_cast<uint32_t*>(&h);
}

__device__ float g_partials[512 * E_DIM];
__device__ unsigned int g_count = 0;

// ================= Kernel 1: GEMM (logits only), w converted in-loop =========
// 16 warps: mw = wid&3 (M: 32 rows), nw = wid>>2 (N: 16 cols).
__global__ __launch_bounds__(NTH_G, 1)
void router_gemm_kernel(const float* __restrict__ x,
                        const float* __restrict__ w,
                        float* __restrict__ out,
                        int N)
{
    extern __shared__ char dsmem[];
    const uint32_t smem_b = smem_u32(dsmem);
    const int tid = threadIdx.x;
    const int wid = tid >> 5;
    const int lane = tid & 31;
    const int n0 = blockIdx.x * BM;

    const int mw = wid & 3;
    const int nw = wid >> 2;

    const uint32_t aRowLo = (uint32_t)((mw * 32 + (lane & 15)) * ROW_BYTES
                                       + (lane >> 4) * 16);
    const uint32_t aRowHi = aRowLo + 16 * ROW_BYTES;
    const uint32_t bOff = (uint32_t)((nw * 16 + ((lane >> 4) & 1) * 8 + (lane & 7)) * ROW_BYTES
                                     + ((lane >> 3) & 1) * 16);

    float4 v[4];          // A staging: 2048 float4/tile -> 4/thread
    float4 wv[2];         // B staging: 64x64 fp32 -> 8 floats/thread

    float acc[2][2][4];
    #pragma unroll
    for (int i = 0; i < 2; i++)
        #pragma unroll
        for (int j = 0; j < 2; j++)
            #pragma unroll
            for (int q = 0; q < 4; q++) acc[i][j][q] = 0.f;

    const int er = tid >> 3, c16 = tid & 7;   // B coords: row 0..63, col-group 0..7

    // prologue: stage tile 0
    #pragma unroll
    for (int p = 0; p < 4; p++) {
        int idx = tid + NTH_G * p;
        int row = idx >> 4, c4 = idx & 15;
        int n = n0 + row; if (n > N - 1) n = N - 1;
        v[p] = *reinterpret_cast<const float4*>(x + (size_t)n * D_DIM + c4 * 4);
    }
    wv[0] = *reinterpret_cast<const float4*>(w + (size_t)er * D_DIM + c16 * 8);
    wv[1] = *reinterpret_cast<const float4*>(w + (size_t)er * D_DIM + c16 * 8 + 4);

    for (int kt = 0; kt < NKT; kt++) {
        __syncthreads();

        // convert fp32 -> fp16, store A and B tiles
        #pragma unroll
        for (int p = 0; p < 4; p++) {
            int idx = tid + NTH_G * p;
            int row = idx >> 4, c4 = idx & 15;
            float4 f = v[p];
            uint32_t u01 = pack_half2(f.x, f.y);
            uint32_t u23 = pack_half2(f.z, f.w);
            uint32_t off = (uint32_t)(row * ROW_BYTES + c4 * 8);
            *reinterpret_cast<uint2*>(dsmem + off) = make_uint2(u01, u23);
        }
        {
            uint4 b;
            b.x = pack_half2(wv[0].x, wv[0].y);
            b.y = pack_half2(wv[0].z, wv[0].w);
            b.z = pack_half2(wv[1].x, wv[1].y);
            b.w = pack_half2(wv[1].z, wv[1].w);
            uint32_t off = (uint32_t)(er * ROW_BYTES + c16 * 16);
            *reinterpret_cast<uint4*>(dsmem + SB_OFF + off) = b;
        }
        __syncthreads();

        // prefetch next tile
        if (kt + 1 < NKT) {
            const int kbase = (kt + 1) * 64;
            #pragma unroll
            for (int p = 0; p < 4; p++) {
                int idx = tid + NTH_G * p;
                int row = idx >> 4, c4 = idx & 15;
                int n = n0 + row; if (n > N - 1) n = N - 1;
                v[p] = *reinterpret_cast<const float4*>(x + (size_t)n * D_DIM + kbase + c4 * 4);
            }
            wv[0] = *reinterpret_cast<const float4*>(w + (size_t)er * D_DIM + kbase + c16 * 8);
            wv[1] = *reinterpret_cast<const float4*>(w + (size_t)er * D_DIM + kbase + c16 * 8 + 4);
        }

        // compute: 4 k16-steps
        const uint32_t aLo = smem_b + aRowLo;
        const uint32_t aHi = smem_b + aRowHi;
        const uint32_t bAd = smem_b + SB_OFF + bOff;

        #pragma unroll
        for (int j = 0; j < 4; j++) {
            uint32_t faL[4], faH[4], fb[4];
            ldsm_x4(faL, aLo + j * 32);
            ldsm_x4(faH, aHi + j * 32);
            ldsm_x4(fb, bAd + j * 32);
            mma_f16(acc[0][0], faL, fb[0], fb[1]);
            mma_f16(acc[0][1], faL, fb[2], fb[3]);
            mma_f16(acc[1][0], faH, fb[0], fb[1]);
            mma_f16(acc[1][1], faH, fb[2], fb[3]);
        }
    }

    // write logits: out[2NE + n*64 + c]
    const size_t NE = (size_t)N * E_DIM;
    float* Lout = out + 2 * NE;
    #pragma unroll
    for (int mh = 0; mh < 2; mh++)
        #pragma unroll
        for (int nh = 0; nh < 2; nh++) {
            int r = n0 + mw * 32 + 16 * mh + (lane >> 2);
            int c = nw * 16 + 8 * nh + 2 * (lane & 3);
            *reinterpret_cast<float2*>(Lout + (size_t)r * E_DIM + c) =
                make_float2(acc[mh][nh][0], acc[mh][nh][1]);
            *reinterpret_cast<float2*>(Lout + (size_t)(r + 8) * E_DIM + c) =
                make_float2(acc[mh][nh][2], acc[mh][nh][3]);
        }
}

// ================= Kernel 2: epilogue =================
__global__ __launch_bounds__(NTH_E)
void router_epilogue_kernel(const float* __restrict__ x,
                            const float* __restrict__ w,
                            float* __restrict__ out,
                            int N)
{
    __shared__ float sPart[8 * E_DIM];
    __shared__ float sq[E_DIM];
    __shared__ int sIsLast;

    const int tid = threadIdx.x;
    const int wid = tid >> 5;
    const int lane = tid & 31;
    const int n0 = blockIdx.x * BM_E;
    const size_t NE = (size_t)N * E_DIM;
    const float* __restrict__ Lin = out + 2 * NE;
    const float NEG_INF = __int_as_float(0xff800000);
    const unsigned FULL = 0xffffffffu;

    float auxA = 0.f, auxB = 0.f;

    for (int tk = wid; tk < BM_E; tk += 8) {
        int n = n0 + tk;
        if (n >= N) continue;  // warp-uniform

        float v0 = Lin[(size_t)n * E_DIM + lane];
        float v1 = Lin[(size_t)n * E_DIM + lane + 32];

        float mx = fmaxf(v0, v1);
        #pragma unroll
        for (int o = 16; o; o >>= 1) mx = fmaxf(mx, __shfl_xor_sync(FULL, mx, o));
        float x0 = expf(v0 - mx), x1 = expf(v1 - mx);
        float s = x0 + x1;
        #pragma unroll
        for (int o = 16; o; o >>= 1) s += __shfl_xor_sync(FULL, s, o);
        float p0 = x0 / s, p1 = x1 / s;
        auxA += p0; auxB += p1;

        // ranks 1..3 only (value desc, index asc on ties)
        int cid[NCAND]; float cv[NCAND];
        float m0v = p0, m1v = p1;
        #pragma unroll
        for (int rko = 0; rko < 3; rko++) {
            float bv; int bix;
            if (m0v >= m1v) { bv = m0v; bix = lane; } else { bv = m1v; bix = lane + 32; }
            #pragma unroll
            for (int o = 16; o; o >>= 1) {
                float ov = __shfl_xor_sync(FULL, bv, o);
                int   oi = __shfl_xor_sync(FULL, bix, o);
                if (ov > bv || (ov == bv && oi < bix)) { bv = ov; bix = oi; }
            }
            cv[rko] = bv; cid[rko] = bix;
            if (lane == bix) m0v = NEG_INF;
            if (lane + 32 == bix) m1v = NEG_INF;
        }

        int bi = cid[0], si = cid[1];
        float bvv = cv[0], sv = cv[1];

        // exact fp32 ordering of top-NCAND when margins tight (warp-uniform, rare)
        if (cv[0] - cv[1] < GAP_TH || cv[1] - cv[2] < GAP_TH) {
            // lazily extend ranks 4..6
            #pragma unroll
            for (int rko = 3; rko < NCAND; rko++) {
                float bv; int bix;
                if (m0v >= m1v) { bv = m0v; bix = lane; } else { bv = m1v; bix = lane + 32; }
                #pragma unroll
                for (int o = 16; o; o >>= 1) {
                    float ov = __shfl_xor_sync(FULL, bv, o);
                    int   oi = __shfl_xor_sync(FULL, bix, o);
                    if (ov > bv || (ov == bv && oi < bix)) { bv = ov; bix = oi; }
                }
                cv[rko] = bv; cid[rko] = bix;
                if (lane == bix) m0v = NEG_INF;
                if (lane + 32 == bix) m1v = NEG_INF;
            }

            float ex[NCAND];
            #pragma unroll
            for (int q = 0; q < NCAND; q++) ex[q] = 0.f;
            const float* xr = x + (size_t)n * D_DIM + lane;
            const float* wr[NCAND];
            #pragma unroll
            for (int q = 0; q < NCAND; q++)
                wr[q] = w + (size_t)cid[q] * D_DIM + lane;
            #pragma unroll 4
            for (int m = 0; m < D_DIM / 32; m++) {
                float xv = __ldg(xr + 32 * m);
                #pragma unroll
                for (int q = 0; q < NCAND; q++)
                    ex[q] = fmaf(xv, __ldg(wr[q] + 32 * m), ex[q]);
            }
            #pragma unroll
            for (int o = 16; o; o >>= 1)
                #pragma unroll
                for (int q = 0; q < NCAND; q++)
                    ex[q] += __shfl_xor_sync(FULL, ex[q], o);
            // sort NCAND by (exact value desc, index asc) — replicated per lane
            int ids[NCAND]; float vs[NCAND];
            #pragma unroll
            for (int q = 0; q < NCAND; q++) { ids[q] = cid[q]; vs[q] = ex[q]; }
            #pragma unroll
            for (int a = 0; a < NCAND - 1; a++)
                #pragma unroll
                for (int b = 0; b < NCAND - 1 - a; b++) {
                    bool sw = (vs[b + 1] > vs[b]) ||
                              (vs[b + 1] == vs[b] && ids[b + 1] < ids[b]);
                    if (sw) {
                        float tv = vs[b]; vs[b] = vs[b + 1]; vs[b + 1] = tv;
                        int ti = ids[b]; ids[b] = ids[b + 1]; ids[b + 1] = ti;
                    }
                }
            bi = ids[0]; si = ids[1];
            float q0 = __shfl_sync(FULL, p0, bi & 31);
            float q1 = __shfl_sync(FULL, p1, bi & 31);
            bvv = (bi < 32) ? q0 : q1;
            q0 = __shfl_sync(FULL, p0, si & 31);
            q1 = __shfl_sync(FULL, p1, si & 31);
            sv = (si < 32) ? q0 : q1;
        }

        float tsum = bvv + sv;
        float pn1 = bvv / tsum, pn2 = sv / tsum;

        size_t rowL = (size_t)n * E_DIM;
        out[3 * NE + rowL + lane]      = p0;
        out[3 * NE + rowL + lane + 32] = p1;
        float d0 = (lane == bi) ? pn1 : ((lane == si) ? pn2 : 0.f);
        float d1 = (lane + 32 == bi) ? pn1 : ((lane + 32 == si) ? pn2 : 0.f);
        out[rowL + lane]           = d0;
        out[rowL + lane + 32]      = d1;
        out[NE + rowL + lane]      = d0;
        out[NE + rowL + lane + 32] = d1;
        if (lane == 0) {
            size_t o5 = 4 * NE + 1 + (size_t)n * 2;
            out[o5]     = (float)bi;
            out[o5 + 1] = (float)si;
            size_t o6 = 4 * NE + 1 + (size_t)N * 2 + (size_t)n * 2;
            out[o6]     = pn1;
            out[o6 + 1] = pn2;
        }
    }

    // per-block expert prob sums + last-block aux loss
    sPart[wid * E_DIM + lane]      = auxA;
    sPart[wid * E_DIM + lane + 32] = auxB;
    __syncthreads();
    if (tid < E_DIM) {
        float ssum = 0.f;
        #pragma unroll
        for (int wd = 0; wd < 8; wd++) ssum += sPart[wd * E_DIM + tid];
        g_partials[blockIdx.x * E_DIM + tid] = ssum;
    }
    __threadfence();
    if (tid == 0) {
        unsigned int prev = atomicAdd(&g_count, 1u);
        sIsLast = (prev == (unsigned int)(gridDim.x - 1)) ? 1 : 0;
    }
    __syncthreads();

    if (sIsLast) {
        __threadfence();
        const int nBlocks = gridDim.x;
        int e = tid & 63;
        int q = tid >> 6;
        float sum = 0.f;
        for (int b = q; b < nBlocks; b += 4) sum += g_partials[b * E_DIM + e];
        sPart[q * E_DIM + e] = sum;
        __syncthreads();
        if (tid < E_DIM) {
            float t = sPart[0 * E_DIM + tid] + sPart[1 * E_DIM + tid]
                    + sPart[2 * E_DIM + tid] + sPart[3 * E_DIM + tid];
            float m = t / (float)N;
            sq[tid] = m * m;
        }
        __syncthreads();
        if (tid == 0) {
            float a = 0.f;
            #pragma unroll
            for (int i = 0; i < E_DIM; i++) a += sq[i];
            out[4 * NE] = a;   // mean_e(E*pbar^2) = sum_e pbar^2
            g_count = 0;       // reset for graph replay
        }
    }
}

extern "C" void kernel_launch(void* const* d_in, const int* in_sizes, int n_in,
                              void* d_out, int out_size)
{
    const float* x = (const float*)d_in[0];   // [N, 2048]
    const float* w = (const float*)d_in[1];   // [64, 2048]
    float* out = (float*)d_out;

    int N = in_sizes[0] / D_DIM;              // 16384
    int nBlkG = (N + BM - 1) / BM;            // 128
    int nBlkE = (N + BM_E - 1) / BM_E;        // 512

    cudaFuncSetAttribute(router_gemm_kernel,
                         cudaFuncAttributeMaxDynamicSharedMemorySize, DSMEM_BYTES);

    router_gemm_kernel<<<nBlkG, NTH_G, DSMEM_BYTES>>>(x, w, out, N);
    router_epilogue_kernel<<<nBlkE, NTH_E>>>(x, w, out, N);
}

// round 15
// speedup vs baseline: 6.0865x; 1.0947x over previous
#include <cuda_runtime.h>
#include <cuda_fp16.h>
#include <math.h>
#include <stdint.h>

// Qwen2.5 MoE expert router — Round 15: R14 design with alignment fix
// (LSTR 65 -> 68: float4 smem accesses must be 16B aligned).
// K1: fp16 HMMA GEMM -> logits. K2: thread-per-token epilogue (no warp
// reductions). K3: queued warp-cooperative exact-fp32 rescue.
// out layout (fp32, reference return order):
//   [0, NE) dispatch | [NE, 2NE) combine | [2NE, 3NE) logits | [3NE, 4NE) probs
//   [4NE] aux_loss | [4NE+1, +2N) top_k_idx (float) | next 2N: top_k_probs_norm

#define D_DIM 2048
#define E_DIM 64
#define BM 128
#define NKT (D_DIM / 64)
#define NTH_G 512
#define GAP_TH 2e-4f
#define NCAND 6

#define ROW_BYTES 144
#define SB_OFF (BM * ROW_BYTES)
#define DSMEM_BYTES (BM * ROW_BYTES + E_DIM * ROW_BYTES)   // 27648

#define E1_TOK 128          // tokens per E1 block (== threads)
#define LSTR 68             // smem row stride (floats); 68%4==0 -> float4 aligned,
                            // 68%32==4 -> LDS.128 8-lane phases conflict-free

__device__ __forceinline__ uint32_t smem_u32(const void* p) {
    uint32_t a;
    asm("{ .reg .u64 t; cvta.to.shared.u64 t, %1; cvt.u32.u64 %0, t; }" : "=r"(a) : "l"(p));
    return a;
}
__device__ __forceinline__ void ldsm_x4(uint32_t* r, uint32_t addr) {
    asm volatile("ldmatrix.sync.aligned.m8n8.x4.shared.b16 {%0,%1,%2,%3}, [%4];"
                 : "=r"(r[0]), "=r"(r[1]), "=r"(r[2]), "=r"(r[3]) : "r"(addr));
}
__device__ __forceinline__ void mma_f16(float* d, const uint32_t* a,
                                        uint32_t b0, uint32_t b1) {
    asm volatile("mma.sync.aligned.m16n8k16.row.col.f32.f16.f16.f32 "
                 "{%0,%1,%2,%3}, {%4,%5,%6,%7}, {%8,%9}, {%0,%1,%2,%3};"
                 : "+f"(d[0]), "+f"(d[1]), "+f"(d[2]), "+f"(d[3])
                 : "r"(a[0]), "r"(a[1]), "r"(a[2]), "r"(a[3]), "r"(b0), "r"(b1));
}
__device__ __forceinline__ uint32_t pack_half2(float lo, float hi) {
    __half2 h = __floats2half2_rn(lo, hi);
    return *reinterpret_cast<uint32_t*>(&h);
}

__device__ float g_partials[128 * E_DIM];
__device__ unsigned int g_count = 0;
__device__ int g_queue[16384];
__device__ unsigned int g_qsize = 0;
__device__ unsigned int g_done = 0;

// ================= Kernel 1: GEMM (logits only) =================
__global__ __launch_bounds__(NTH_G, 1)
void router_gemm_kernel(const float* __restrict__ x,
                        const float* __restrict__ w,
                        float* __restrict__ out,
                        int N)
{
    extern __shared__ char dsmem[];
    const uint32_t smem_b = smem_u32(dsmem);
    const int tid = threadIdx.x;
    const int wid = tid >> 5;
    const int lane = tid & 31;
    const int n0 = blockIdx.x * BM;

    const int mw = wid & 3;
    const int nw = wid >> 2;

    const uint32_t aRowLo = (uint32_t)((mw * 32 + (lane & 15)) * ROW_BYTES
                                       + (lane >> 4) * 16);
    const uint32_t aRowHi = aRowLo + 16 * ROW_BYTES;
    const uint32_t bOff = (uint32_t)((nw * 16 + ((lane >> 4) & 1) * 8 + (lane & 7)) * ROW_BYTES
                                     + ((lane >> 3) & 1) * 16);

    float4 v[4];
    float4 wv[2];

    float acc[2][2][4];
    #pragma unroll
    for (int i = 0; i < 2; i++)
        #pragma unroll
        for (int j = 0; j < 2; j++)
            #pragma unroll
            for (int q = 0; q < 4; q++) acc[i][j][q] = 0.f;

    const int er = tid >> 3, c16 = tid & 7;

    #pragma unroll
    for (int p = 0; p < 4; p++) {
        int idx = tid + NTH_G * p;
        int row = idx >> 4, c4 = idx & 15;
        int n = n0 + row; if (n > N - 1) n = N - 1;
        v[p] = *reinterpret_cast<const float4*>(x + (size_t)n * D_DIM + c4 * 4);
    }
    wv[0] = *reinterpret_cast<const float4*>(w + (size_t)er * D_DIM + c16 * 8);
    wv[1] = *reinterpret_cast<const float4*>(w + (size_t)er * D_DIM + c16 * 8 + 4);

    for (int kt = 0; kt < NKT; kt++) {
        __syncthreads();

        #pragma unroll
        for (int p = 0; p < 4; p++) {
            int idx = tid + NTH_G * p;
            int row = idx >> 4, c4 = idx & 15;
            float4 f = v[p];
            uint32_t u01 = pack_half2(f.x, f.y);
            uint32_t u23 = pack_half2(f.z, f.w);
            uint32_t off = (uint32_t)(row * ROW_BYTES + c4 * 8);
            *reinterpret_cast<uint2*>(dsmem + off) = make_uint2(u01, u23);
        }
        {
            uint4 b;
            b.x = pack_half2(wv[0].x, wv[0].y);
            b.y = pack_half2(wv[0].z, wv[0].w);
            b.z = pack_half2(wv[1].x, wv[1].y);
            b.w = pack_half2(wv[1].z, wv[1].w);
            uint32_t off = (uint32_t)(er * ROW_BYTES + c16 * 16);
            *reinterpret_cast<uint4*>(dsmem + SB_OFF + off) = b;
        }
        __syncthreads();

        if (kt + 1 < NKT) {
            const int kbase = (kt + 1) * 64;
            #pragma unroll
            for (int p = 0; p < 4; p++) {
                int idx = tid + NTH_G * p;
                int row = idx >> 4, c4 = idx & 15;
                int n = n0 + row; if (n > N - 1) n = N - 1;
                v[p] = *reinterpret_cast<const float4*>(x + (size_t)n * D_DIM + kbase + c4 * 4);
            }
            wv[0] = *reinterpret_cast<const float4*>(w + (size_t)er * D_DIM + kbase + c16 * 8);
            wv[1] = *reinterpret_cast<const float4*>(w + (size_t)er * D_DIM + kbase + c16 * 8 + 4);
        }

        const uint32_t aLo = smem_b + aRowLo;
        const uint32_t aHi = smem_b + aRowHi;
        const uint32_t bAd = smem_b + SB_OFF + bOff;

        #pragma unroll
        for (int j = 0; j < 4; j++) {
            uint32_t faL[4], faH[4], fb[4];
            ldsm_x4(faL, aLo + j * 32);
            ldsm_x4(faH, aHi + j * 32);
            ldsm_x4(fb, bAd + j * 32);
            mma_f16(acc[0][0], faL, fb[0], fb[1]);
            mma_f16(acc[0][1], faL, fb[2], fb[3]);
            mma_f16(acc[1][0], faH, fb[0], fb[1]);
            mma_f16(acc[1][1], faH, fb[2], fb[3]);
        }
    }

    const size_t NE = (size_t)N * E_DIM;
    float* Lout = out + 2 * NE;
    #pragma unroll
    for (int mh = 0; mh < 2; mh++)
        #pragma unroll
        for (int nh = 0; nh < 2; nh++) {
            int r = n0 + mw * 32 + 16 * mh + (lane >> 2);
            int c = nw * 16 + 8 * nh + 2 * (lane & 3);
            *reinterpret_cast<float2*>(Lout + (size_t)r * E_DIM + c) =
                make_float2(acc[mh][nh][0], acc[mh][nh][1]);
            *reinterpret_cast<float2*>(Lout + (size_t)(r + 8) * E_DIM + c) =
                make_float2(acc[mh][nh][2], acc[mh][nh][3]);
        }
}

// ================= Kernel 2: thread-per-token epilogue =================
__global__ __launch_bounds__(E1_TOK)
void router_epilogue_kernel(float* __restrict__ out, int N)
{
    __shared__ float Lg[E1_TOK * LSTR];   // 34816 B
    __shared__ float sAux[2 * E_DIM];
    __shared__ float sq[E_DIM];
    __shared__ int sIsLast;

    const int tid = threadIdx.x;
    const int lane = tid & 31;
    const int n0 = blockIdx.x * E1_TOK;
    const int n = n0 + tid;
    const size_t NE = (size_t)N * E_DIM;
    const float* __restrict__ Lin = out + 2 * NE;
    const unsigned FULL = 0xffffffffu;

    // phase 1: coalesced load logits -> smem rows
    #pragma unroll
    for (int p = 0; p < 16; p++) {
        int idx = tid + E1_TOK * p;
        int tok = idx >> 4, c4 = idx & 15;
        float4 f = *reinterpret_cast<const float4*>(Lin + (size_t)(n0 + tok) * E_DIM + c4 * 4);
        *reinterpret_cast<float4*>(&Lg[tok * LSTR + c4 * 4]) = f;
    }
    __syncthreads();

    // phase 2: own row — max
    float mx = -1e30f;
    #pragma unroll
    for (int c = 0; c < 16; c++) {
        float4 f = *reinterpret_cast<const float4*>(&Lg[tid * LSTR + c * 4]);
        mx = fmaxf(mx, fmaxf(fmaxf(f.x, f.y), fmaxf(f.z, f.w)));
    }
    // phase 3: exp + sum (store exp back)
    float s = 0.f;
    #pragma unroll
    for (int c = 0; c < 16; c++) {
        float4 f = *reinterpret_cast<float4*>(&Lg[tid * LSTR + c * 4]);
        f.x = expf(f.x - mx); f.y = expf(f.y - mx);
        f.z = expf(f.z - mx); f.w = expf(f.w - mx);
        s += (f.x + f.y) + (f.z + f.w);
        *reinterpret_cast<float4*>(&Lg[tid * LSTR + c * 4]) = f;
    }
    float inv = 1.f / s;
    // phase 4: scale + top-3 scan (strict > => smallest index on ties)
    float v1 = -1.f, v2 = -1.f, v3 = -1.f;
    int i1 = 0, i2 = 0, i3 = 0;
    #pragma unroll
    for (int c = 0; c < 16; c++) {
        float4 f = *reinterpret_cast<float4*>(&Lg[tid * LSTR + c * 4]);
        f.x *= inv; f.y *= inv; f.z *= inv; f.w *= inv;
        float pv[4] = {f.x, f.y, f.z, f.w};
        #pragma unroll
        for (int j = 0; j < 4; j++) {
            float p = pv[j]; int ci = c * 4 + j;
            if (p > v1)      { v3 = v2; i3 = i2; v2 = v1; i2 = i1; v1 = p; i1 = ci; }
            else if (p > v2) { v3 = v2; i3 = i2; v2 = p; i2 = ci; }
            else if (p > v3) { v3 = p; i3 = ci; }
        }
        *reinterpret_cast<float4*>(&Lg[tid * LSTR + c * 4]) = f;
    }
    __syncthreads();

    // phase 5: coalesced probs store + aux column sums
    #pragma unroll
    for (int p = 0; p < 16; p++) {
        int idx = tid + E1_TOK * p;
        int tok = idx >> 4, c4 = idx & 15;
        float4 f = *reinterpret_cast<const float4*>(&Lg[tok * LSTR + c4 * 4]);
        *reinterpret_cast<float4*>(out + 3 * NE + (size_t)(n0 + tok) * E_DIM + c4 * 4) = f;
    }
    {
        int e = tid & 63, half = tid >> 6;
        float a = 0.f;
        #pragma unroll
        for (int r = 0; r < 64; r++)
            a += Lg[(half * 64 + r) * LSTR + e];
        sAux[half * E_DIM + e] = a;
    }

    // per-token small outputs + rescue flag/queue
    float tsum = v1 + v2;
    float pn1 = v1 / tsum, pn2 = v2 / tsum;
    {
        size_t o5 = 4 * NE + 1 + (size_t)n * 2;
        out[o5] = (float)i1; out[o5 + 1] = (float)i2;
        size_t o6 = 4 * NE + 1 + (size_t)N * 2 + (size_t)n * 2;
        out[o6] = pn1; out[o6 + 1] = pn2;
    }
    {
        bool flag = (v1 - v2 < GAP_TH) || (v2 - v3 < GAP_TH);
        unsigned mask = __ballot_sync(FULL, flag);
        if (mask) {
            int ldr = __ffs(mask) - 1;
            unsigned base = 0;
            if (lane == ldr) base = atomicAdd(&g_qsize, (unsigned)__popc(mask));
            base = __shfl_sync(FULL, base, ldr);
            if (flag) {
                int pos = __popc(mask & ((1u << lane) - 1u));
                g_queue[base + pos] = n;
            }
        }
    }
    __syncthreads();   // phase-5 reads of Lg done

    // phase 6: dispatch row in smem (zero + scatter own row)
    #pragma unroll
    for (int c = 0; c < 16; c++)
        *reinterpret_cast<float4*>(&Lg[tid * LSTR + c * 4]) = make_float4(0.f, 0.f, 0.f, 0.f);
    Lg[tid * LSTR + i1] = pn1;
    Lg[tid * LSTR + i2] = pn2;
    __syncthreads();

    // phase 7: coalesced dispatch + combine store
    #pragma unroll
    for (int p = 0; p < 16; p++) {
        int idx = tid + E1_TOK * p;
        int tok = idx >> 4, c4 = idx & 15;
        float4 f = *reinterpret_cast<const float4*>(&Lg[tok * LSTR + c4 * 4]);
        *reinterpret_cast<float4*>(out + (size_t)(n0 + tok) * E_DIM + c4 * 4) = f;
        *reinterpret_cast<float4*>(out + NE + (size_t)(n0 + tok) * E_DIM + c4 * 4) = f;
    }

    // aux partials
    if (tid < E_DIM)
        g_partials[blockIdx.x * E_DIM + tid] = sAux[tid] + sAux[E_DIM + tid];
    __threadfence();
    if (tid == 0) {
        unsigned int prev = atomicAdd(&g_count, 1u);
        sIsLast = (prev == (unsigned int)(gridDim.x - 1)) ? 1 : 0;
    }
    __syncthreads();

    if (sIsLast) {
        __threadfence();
        int e = tid & 63, q = tid >> 6;   // q in {0,1}
        float sum = 0.f;
        for (int b = q; b < (int)gridDim.x; b += 2) sum += g_partials[b * E_DIM + e];
        sAux[q * E_DIM + e] = sum;
        __syncthreads();
        if (tid < E_DIM) {
            float m = (sAux[tid] + sAux[E_DIM + tid]) / (float)N;
            sq[tid] = m * m;
        }
        __syncthreads();
        if (tid == 0) {
            float a = 0.f;
            #pragma unroll
            for (int i = 0; i < E_DIM; i++) a += sq[i];
            out[4 * NE] = a;
            g_count = 0;
        }
    }
}

// ================= Kernel 3: warp-cooperative exact rescue =================
__global__ __launch_bounds__(256)
void router_rescue_kernel(const float* __restrict__ x,
                          const float* __restrict__ w,
                          float* __restrict__ out,
                          int N)
{
    const int tid = threadIdx.x;
    const int lane = tid & 31;
    const int gw = (blockIdx.x * 256 + tid) >> 5;
    const int nwarps = (gridDim.x * 256) >> 5;
    const size_t NE = (size_t)N * E_DIM;
    const float NEG_INF = __int_as_float(0xff800000);
    const unsigned FULL = 0xffffffffu;

    const int qn = (int)g_qsize;

    for (int qi = gw; qi < qn; qi += nwarps) {
        int n = g_queue[qi];
        float p0 = out[3 * NE + (size_t)n * E_DIM + lane];
        float p1 = out[3 * NE + (size_t)n * E_DIM + lane + 32];

        // ranks 1..NCAND by prob (value desc, index asc)
        int cid[NCAND]; float m0v = p0, m1v = p1;
        #pragma unroll
        for (int rko = 0; rko < NCAND; rko++) {
            float bv; int bix;
            if (m0v >= m1v) { bv = m0v; bix = lane; } else { bv = m1v; bix = lane + 32; }
            #pragma unroll
            for (int o = 16; o; o >>= 1) {
                float ov = __shfl_xor_sync(FULL, bv, o);
                int   oi = __shfl_xor_sync(FULL, bix, o);
                if (ov > bv || (ov == bv && oi < bix)) { bv = ov; bix = oi; }
            }
            cid[rko] = bix;
            if (lane == bix) m0v = NEG_INF;
            if (lane + 32 == bix) m1v = NEG_INF;
        }
        int pbi = cid[0], psi = cid[1];   // provisional (matches E1's scan)

        // exact fp32 logits for candidates
        float ex[NCAND];
        #pragma unroll
        for (int q = 0; q < NCAND; q++) ex[q] = 0.f;
        const float* xr = x + (size_t)n * D_DIM + lane;
        const float* wr[NCAND];
        #pragma unroll
        for (int q = 0; q < NCAND; q++) wr[q] = w + (size_t)cid[q] * D_DIM + lane;
        #pragma unroll 4
        for (int m = 0; m < D_DIM / 32; m++) {
            float xv = __ldg(xr + 32 * m);
            #pragma unroll
            for (int q = 0; q < NCAND; q++)
                ex[q] = fmaf(xv, __ldg(wr[q] + 32 * m), ex[q]);
        }
        #pragma unroll
        for (int o = 16; o; o >>= 1)
            #pragma unroll
            for (int q = 0; q < NCAND; q++)
                ex[q] += __shfl_xor_sync(FULL, ex[q], o);

        int ids[NCAND]; float vs[NCAND];
        #pragma unroll
        for (int q = 0; q < NCAND; q++) { ids[q] = cid[q]; vs[q] = ex[q]; }
        #pragma unroll
        for (int a = 0; a < NCAND - 1; a++)
            #pragma unroll
            for (int b = 0; b < NCAND - 1 - a; b++) {
                bool sw = (vs[b + 1] > vs[b]) ||
                          (vs[b + 1] == vs[b] && ids[b + 1] < ids[b]);
                if (sw) {
                    float tv = vs[b]; vs[b] = vs[b + 1]; vs[b + 1] = tv;
                    int ti = ids[b]; ids[b] = ids[b + 1]; ids[b + 1] = ti;
                }
            }
        int nbi = ids[0], nsi = ids[1];

        // prob values of selected experts
        float q0 = __shfl_sync(FULL, p0, nbi & 31);
        float q1 = __shfl_sync(FULL, p1, nbi & 31);
        float bvv = (nbi < 32) ? q0 : q1;
        q0 = __shfl_sync(FULL, p0, nsi & 31);
        q1 = __shfl_sync(FULL, p1, nsi & 31);
        float sv = (nsi < 32) ? q0 : q1;
        float tsum = bvv + sv;
        float pn1 = bvv / tsum, pn2 = sv / tsum;

        if (lane == 0) {
            size_t rowL = (size_t)n * E_DIM;
            out[rowL + pbi] = 0.f;      out[rowL + psi] = 0.f;
            out[NE + rowL + pbi] = 0.f; out[NE + rowL + psi] = 0.f;
            out[rowL + nbi] = pn1;      out[rowL + nsi] = pn2;
            out[NE + rowL + nbi] = pn1; out[NE + rowL + nsi] = pn2;
            size_t o5 = 4 * NE + 1 + (size_t)n * 2;
            out[o5] = (float)nbi; out[o5 + 1] = (float)nsi;
            size_t o6 = 4 * NE + 1 + (size_t)N * 2 + (size_t)n * 2;
            out[o6] = pn1; out[o6 + 1] = pn2;
        }
    }

    __syncthreads();
    __threadfence();
    if (tid == 0) {
        unsigned int d = atomicAdd(&g_done, 1u);
        if (d == (unsigned int)(gridDim.x - 1)) { g_qsize = 0; g_done = 0; }
    }
}

extern "C" void kernel_launch(void* const* d_in, const int* in_sizes, int n_in,
                              void* d_out, int out_size)
{
    const float* x = (const float*)d_in[0];   // [N, 2048]
    const float* w = (const float*)d_in[1];   // [64, 2048]
    float* out = (float*)d_out;

    int N = in_sizes[0] / D_DIM;              // 16384
    int nBlkG = (N + BM - 1) / BM;            // 128
    int nBlkE = (N + E1_TOK - 1) / E1_TOK;    // 128

    cudaFuncSetAttribute(router_gemm_kernel,
                         cudaFuncAttributeMaxDynamicSharedMemorySize, DSMEM_BYTES);

    router_gemm_kernel<<<nBlkG, NTH_G, DSMEM_BYTES>>>(x, w, out, N);
    router_epilogue_kernel<<<nBlkE, E1_TOK>>>(out, N);
    router_rescue_kernel<<<128, 256>>>(x, w, out, N);
}

// round 16
// speedup vs baseline: 6.3890x; 1.0497x over previous
#include <cuda_runtime.h>
#include <cuda_fp16.h>
#include <math.h>
#include <stdint.h>

// Qwen2.5 MoE expert router — Round 16: fused fp16-HMMA GEMM + thread-per-token
// epilogue in one kernel (double-buffered smem, 1 sync/ktile), plus queued
// warp-cooperative exact-fp32 rescue kernel. Last-block aux loss fused.
// out layout (fp32, reference return order):
//   [0, NE) dispatch | [NE, 2NE) combine | [2NE, 3NE) logits | [3NE, 4NE) probs
//   [4NE] aux_loss | [4NE+1, +2N) top_k_idx (float) | next 2N: top_k_probs_norm

#define D_DIM 2048
#define E_DIM 64
#define BM 128
#define NKT (D_DIM / 64)
#define NTH_G 512
#define GAP_TH 2e-4f
#define NCAND 6

#define ROW_BYTES 144
#define BUF_BYTES (BM * ROW_BYTES + E_DIM * ROW_BYTES)    // 27648
#define SB_OFF (BM * ROW_BYTES)                            // 18432 (within buf)
#define LSTR 68                                            // floats; 16B-aligned rows
#define LG_BYTES (BM * LSTR * 4)                           // 34816
#define DSMEM_BYTES (2 * BUF_BYTES)                        // 55296 > LG_BYTES

__device__ __forceinline__ uint32_t smem_u32(const void* p) {
    uint32_t a;
    asm("{ .reg .u64 t; cvta.to.shared.u64 t, %1; cvt.u32.u64 %0, t; }" : "=r"(a) : "l"(p));
    return a;
}
__device__ __forceinline__ void ldsm_x4(uint32_t* r, uint32_t addr) {
    asm volatile("ldmatrix.sync.aligned.m8n8.x4.shared.b16 {%0,%1,%2,%3}, [%4];"
                 : "=r"(r[0]), "=r"(r[1]), "=r"(r[2]), "=r"(r[3]) : "r"(addr));
}
__device__ __forceinline__ void mma_f16(float* d, const uint32_t* a,
                                        uint32_t b0, uint32_t b1) {
    asm volatile("mma.sync.aligned.m16n8k16.row.col.f32.f16.f16.f32 "
                 "{%0,%1,%2,%3}, {%4,%5,%6,%7}, {%8,%9}, {%0,%1,%2,%3};"
                 : "+f"(d[0]), "+f"(d[1]), "+f"(d[2]), "+f"(d[3])
                 : "r"(a[0]), "r"(a[1]), "r"(a[2]), "r"(a[3]), "r"(b0), "r"(b1));
}
__device__ __forceinline__ uint32_t pack_half2(float lo, float hi) {
    __half2 h = __floats2half2_rn(lo, hi);
    return *reinterpret_cast<uint32_t*>(&h);
}

__device__ float g_partials[128 * E_DIM];
__device__ unsigned int g_count = 0;
__device__ int g_queue[16384];
__device__ unsigned int g_qsize = 0;
__device__ unsigned int g_done = 0;

// ============ Kernel 1: fused GEMM + epilogue ============
__global__ __launch_bounds__(NTH_G, 1)
void router_fused_kernel(const float* __restrict__ x,
                         const float* __restrict__ w,
                         float* __restrict__ out,
                         int N)
{
    extern __shared__ char dsmem[];
    __shared__ float sAux[8 * E_DIM];
    __shared__ float sq[E_DIM];
    __shared__ int sIsLast;

    const uint32_t smem_b = smem_u32(dsmem);
    const int tid = threadIdx.x;
    const int wid = tid >> 5;
    const int lane = tid & 31;
    const int n0 = blockIdx.x * BM;
    const size_t NE = (size_t)N * E_DIM;
    const unsigned FULL = 0xffffffffu;

    const int mw = wid & 3;
    const int nw = wid >> 2;

    const uint32_t aRowLo = (uint32_t)((mw * 32 + (lane & 15)) * ROW_BYTES
                                       + (lane >> 4) * 16);
    const uint32_t aRowHi = aRowLo + 16 * ROW_BYTES;
    const uint32_t bOff = (uint32_t)((nw * 16 + ((lane >> 4) & 1) * 8 + (lane & 7)) * ROW_BYTES
                                     + ((lane >> 3) & 1) * 16);

    float4 v[4];
    float4 wv[2];

    float acc[2][2][4];
    #pragma unroll
    for (int i = 0; i < 2; i++)
        #pragma unroll
        for (int j = 0; j < 2; j++)
            #pragma unroll
            for (int q = 0; q < 4; q++) acc[i][j][q] = 0.f;

    const int er = tid >> 3, c16 = tid & 7;

    // ---- load tile 0 ----
    #pragma unroll
    for (int p = 0; p < 4; p++) {
        int idx = tid + NTH_G * p;
        int row = idx >> 4, c4 = idx & 15;
        int n = n0 + row; if (n > N - 1) n = N - 1;
        v[p] = *reinterpret_cast<const float4*>(x + (size_t)n * D_DIM + c4 * 4);
    }
    wv[0] = *reinterpret_cast<const float4*>(w + (size_t)er * D_DIM + c16 * 8);
    wv[1] = *reinterpret_cast<const float4*>(w + (size_t)er * D_DIM + c16 * 8 + 4);

    // ---- store tile 0 -> buf0, then issue loads for tile 1 ----
    {
        char* base = dsmem;
        #pragma unroll
        for (int p = 0; p < 4; p++) {
            int idx = tid + NTH_G * p;
            int row = idx >> 4, c4 = idx & 15;
            float4 f = v[p];
            uint32_t off = (uint32_t)(row * ROW_BYTES + c4 * 8);
            *reinterpret_cast<uint2*>(base + off) =
                make_uint2(pack_half2(f.x, f.y), pack_half2(f.z, f.w));
        }
        uint4 b;
        b.x = pack_half2(wv[0].x, wv[0].y);
        b.y = pack_half2(wv[0].z, wv[0].w);
        b.z = pack_half2(wv[1].x, wv[1].y);
        b.w = pack_half2(wv[1].z, wv[1].w);
        *reinterpret_cast<uint4*>(base + SB_OFF + (uint32_t)(er * ROW_BYTES + c16 * 16)) = b;
    }
    {
        const int kbase = 64;
        #pragma unroll
        for (int p = 0; p < 4; p++) {
            int idx = tid + NTH_G * p;
            int row = idx >> 4, c4 = idx & 15;
            int n = n0 + row; if (n > N - 1) n = N - 1;
            v[p] = *reinterpret_cast<const float4*>(x + (size_t)n * D_DIM + kbase + c4 * 4);
        }
        wv[0] = *reinterpret_cast<const float4*>(w + (size_t)er * D_DIM + kbase + c16 * 8);
        wv[1] = *reinterpret_cast<const float4*>(w + (size_t)er * D_DIM + kbase + c16 * 8 + 4);
    }
    __syncthreads();

    // ---- main loop: 1 sync per ktile ----
    for (int kt = 0; kt < NKT; kt++) {
        // store tile kt+1 into other buffer (regs loaded last iteration)
        if (kt + 1 < NKT) {
            char* base = dsmem + ((kt + 1) & 1) * BUF_BYTES;
            #pragma unroll
            for (int p = 0; p < 4; p++) {
                int idx = tid + NTH_G * p;
                int row = idx >> 4, c4 = idx & 15;
                float4 f = v[p];
                uint32_t off = (uint32_t)(row * ROW_BYTES + c4 * 8);
                *reinterpret_cast<uint2*>(base + off) =
                    make_uint2(pack_half2(f.x, f.y), pack_half2(f.z, f.w));
            }
            uint4 b;
            b.x = pack_half2(wv[0].x, wv[0].y);
            b.y = pack_half2(wv[0].z, wv[0].w);
            b.z = pack_half2(wv[1].x, wv[1].y);
            b.w = pack_half2(wv[1].z, wv[1].w);
            *reinterpret_cast<uint4*>(base + SB_OFF + (uint32_t)(er * ROW_BYTES + c16 * 16)) = b;
        }
        // issue loads for tile kt+2
        if (kt + 2 < NKT) {
            const int kbase = (kt + 2) * 64;
            #pragma unroll
            for (int p = 0; p < 4; p++) {
                int idx = tid + NTH_G * p;
                int row = idx >> 4, c4 = idx & 15;
                int n = n0 + row; if (n > N - 1) n = N - 1;
                v[p] = *reinterpret_cast<const float4*>(x + (size_t)n * D_DIM + kbase + c4 * 4);
            }
            wv[0] = *reinterpret_cast<const float4*>(w + (size_t)er * D_DIM + kbase + c16 * 8);
            wv[1] = *reinterpret_cast<const float4*>(w + (size_t)er * D_DIM + kbase + c16 * 8 + 4);
        }

        // compute tile kt from buf[kt&1]
        const uint32_t bb = smem_b + (kt & 1) * BUF_BYTES;
        const uint32_t aLo = bb + aRowLo;
        const uint32_t aHi = bb + aRowHi;
        const uint32_t bAd = bb + SB_OFF + bOff;
        #pragma unroll
        for (int j = 0; j < 4; j++) {
            uint32_t faL[4], faH[4], fb[4];
            ldsm_x4(faL, aLo + j * 32);
            ldsm_x4(faH, aHi + j * 32);
            ldsm_x4(fb, bAd + j * 32);
            mma_f16(acc[0][0], faL, fb[0], fb[1]);
            mma_f16(acc[0][1], faL, fb[2], fb[3]);
            mma_f16(acc[1][0], faH, fb[0], fb[1]);
            mma_f16(acc[1][1], faH, fb[2], fb[3]);
        }
        __syncthreads();
    }

    // ---- fragments -> smem Lg (aliases A/B buffers; sync above guarantees done) ----
    float* Lg = reinterpret_cast<float*>(dsmem);
    #pragma unroll
    for (int mh = 0; mh < 2; mh++)
        #pragma unroll
        for (int nh = 0; nh < 2; nh++) {
            int r = mw * 32 + 16 * mh + (lane >> 2);
            int c = nw * 16 + 8 * nh + 2 * (lane & 3);
            *reinterpret_cast<float2*>(&Lg[r * LSTR + c]) =
                make_float2(acc[mh][nh][0], acc[mh][nh][1]);
            *reinterpret_cast<float2*>(&Lg[(r + 8) * LSTR + c]) =
                make_float2(acc[mh][nh][2], acc[mh][nh][3]);
        }
    __syncthreads();

    // ---- coalesced logits store (all 512 threads) ----
    #pragma unroll
    for (int p = 0; p < 4; p++) {
        int idx = tid + NTH_G * p;
        int tok = idx >> 4, c4 = idx & 15;
        float4 f = *reinterpret_cast<const float4*>(&Lg[tok * LSTR + c4 * 4]);
        *reinterpret_cast<float4*>(out + 2 * NE + (size_t)(n0 + tok) * E_DIM + c4 * 4) = f;
    }

    // ---- per-token softmax + top-3 scan (tid < 128, one token each) ----
    float v1 = -1.f, v2 = -1.f, v3 = -1.f;
    int i1 = 0, i2 = 0;
    float pn1 = 0.f, pn2 = 0.f;
    if (tid < BM) {
        float mx = -1e30f;
        #pragma unroll
        for (int c = 0; c < 16; c++) {
            float4 f = *reinterpret_cast<const float4*>(&Lg[tid * LSTR + c * 4]);
            mx = fmaxf(mx, fmaxf(fmaxf(f.x, f.y), fmaxf(f.z, f.w)));
        }
        float s = 0.f;
        #pragma unroll
        for (int c = 0; c < 16; c++) {
            float4 f = *reinterpret_cast<float4*>(&Lg[tid * LSTR + c * 4]);
            f.x = expf(f.x - mx); f.y = expf(f.y - mx);
            f.z = expf(f.z - mx); f.w = expf(f.w - mx);
            s += (f.x + f.y) + (f.z + f.w);
            *reinterpret_cast<float4*>(&Lg[tid * LSTR + c * 4]) = f;
        }
        float inv = 1.f / s;
        #pragma unroll
        for (int c = 0; c < 16; c++) {
            float4 f = *reinterpret_cast<float4*>(&Lg[tid * LSTR + c * 4]);
            f.x *= inv; f.y *= inv; f.z *= inv; f.w *= inv;
            float pv[4] = {f.x, f.y, f.z, f.w};
            #pragma unroll
            for (int j = 0; j < 4; j++) {
                float p = pv[j]; int ci = c * 4 + j;
                if (p > v1)      { v3 = v2; v2 = v1; i2 = i1; v1 = p; i1 = ci; }
                else if (p > v2) { v3 = v2; v2 = p; i2 = ci; }
                else if (p > v3) { v3 = p; }
            }
            *reinterpret_cast<float4*>(&Lg[tid * LSTR + c * 4]) = f;
        }
        float tsum = v1 + v2;
        pn1 = v1 / tsum; pn2 = v2 / tsum;

        int n = n0 + tid;
        size_t o5 = 4 * NE + 1 + (size_t)n * 2;
        out[o5] = (float)i1; out[o5 + 1] = (float)i2;
        size_t o6 = 4 * NE + 1 + (size_t)N * 2 + (size_t)n * 2;
        out[o6] = pn1; out[o6 + 1] = pn2;

        bool flag = (v1 - v2 < GAP_TH) || (v2 - v3 < GAP_TH);
        unsigned mask = __ballot_sync(FULL, flag);   // warps 0-3 fully active here
        if (mask) {
            int ldr = __ffs(mask) - 1;
            unsigned base = 0;
            if (lane == ldr) base = atomicAdd(&g_qsize, (unsigned)__popc(mask));
            base = __shfl_sync(FULL, base, ldr);
            if (flag) {
                int pos = __popc(mask & ((1u << lane) - 1u));
                g_queue[base + pos] = n;
            }
        }
    }
    __syncthreads();

    // ---- coalesced probs store + aux column sums (all 512) ----
    #pragma unroll
    for (int p = 0; p < 4; p++) {
        int idx = tid + NTH_G * p;
        int tok = idx >> 4, c4 = idx & 15;
        float4 f = *reinterpret_cast<const float4*>(&Lg[tok * LSTR + c4 * 4]);
        *reinterpret_cast<float4*>(out + 3 * NE + (size_t)(n0 + tok) * E_DIM + c4 * 4) = f;
    }
    {
        int e = tid & 63, g = tid >> 6;   // 8 groups x 16 rows
        float a = 0.f;
        #pragma unroll
        for (int r = 0; r < 16; r++)
            a += Lg[(g * 16 + r) * LSTR + e];
        sAux[g * E_DIM + e] = a;
    }
    __syncthreads();

    // ---- dispatch rows in smem (zero + scatter), then coalesced store ----
    if (tid < BM) {
        #pragma unroll
        for (int c = 0; c < 16; c++)
            *reinterpret_cast<float4*>(&Lg[tid * LSTR + c * 4]) =
                make_float4(0.f, 0.f, 0.f, 0.f);
        Lg[tid * LSTR + i1] = pn1;
        Lg[tid * LSTR + i2] = pn2;
    }
    __syncthreads();
    #pragma unroll
    for (int p = 0; p < 4; p++) {
        int idx = tid + NTH_G * p;
        int tok = idx >> 4, c4 = idx & 15;
        float4 f = *reinterpret_cast<const float4*>(&Lg[tok * LSTR + c4 * 4]);
        *reinterpret_cast<float4*>(out + (size_t)(n0 + tok) * E_DIM + c4 * 4) = f;
        *reinterpret_cast<float4*>(out + NE + (size_t)(n0 + tok) * E_DIM + c4 * 4) = f;
    }

    // ---- aux partials + last-block reduction ----
    if (tid < E_DIM) {
        float ssum = 0.f;
        #pragma unroll
        for (int g = 0; g < 8; g++) ssum += sAux[g * E_DIM + tid];
        g_partials[blockIdx.x * E_DIM + tid] = ssum;
    }
    __threadfence();
    if (tid == 0) {
        unsigned int prev = atomicAdd(&g_count, 1u);
        sIsLast = (prev == (unsigned int)(gridDim.x - 1)) ? 1 : 0;
    }
    __syncthreads();

    if (sIsLast) {
        __threadfence();
        int e = tid & 63, q = tid >> 6;   // 8 groups
        float sum = 0.f;
        for (int b = q; b < (int)gridDim.x; b += 8) sum += g_partials[b * E_DIM + e];
        sAux[q * E_DIM + e] = sum;
        __syncthreads();
        if (tid < E_DIM) {
            float t = 0.f;
            #pragma unroll
            for (int g = 0; g < 8; g++) t += sAux[g * E_DIM + tid];
            float m = t / (float)N;
            sq[tid] = m * m;
        }
        __syncthreads();
        if (tid == 0) {
            float a = 0.f;
            #pragma unroll
            for (int i = 0; i < E_DIM; i++) a += sq[i];
            out[4 * NE] = a;
            g_count = 0;
        }
    }
}

// ============ Kernel 2: warp-cooperative exact rescue ============
__global__ __launch_bounds__(256)
void router_rescue_kernel(const float* __restrict__ x,
                          const float* __restrict__ w,
                          float* __restrict__ out,
                          int N)
{
    const int tid = threadIdx.x;
    const int lane = tid & 31;
    const int gw = (blockIdx.x * 256 + tid) >> 5;
    const int nwarps = (gridDim.x * 256) >> 5;
    const size_t NE = (size_t)N * E_DIM;
    const float NEG_INF = __int_as_float(0xff800000);
    const unsigned FULL = 0xffffffffu;

    const int qn = (int)g_qsize;

    for (int qi = gw; qi < qn; qi += nwarps) {
        int n = g_queue[qi];
        float p0 = out[3 * NE + (size_t)n * E_DIM + lane];
        float p1 = out[3 * NE + (size_t)n * E_DIM + lane + 32];

        int cid[NCAND]; float m0v = p0, m1v = p1;
        #pragma unroll
        for (int rko = 0; rko < NCAND; rko++) {
            float bv; int bix;
            if (m0v >= m1v) { bv = m0v; bix = lane; } else { bv = m1v; bix = lane + 32; }
            #pragma unroll
            for (int o = 16; o; o >>= 1) {
                float ov = __shfl_xor_sync(FULL, bv, o);
                int   oi = __shfl_xor_sync(FULL, bix, o);
                if (ov > bv || (ov == bv && oi < bix)) { bv = ov; bix = oi; }
            }
            cid[rko] = bix;
            if (lane == bix) m0v = NEG_INF;
            if (lane + 32 == bix) m1v = NEG_INF;
        }
        int pbi = cid[0], psi = cid[1];

        float ex[NCAND];
        #pragma unroll
        for (int q = 0; q < NCAND; q++) ex[q] = 0.f;
        const float* xr = x + (size_t)n * D_DIM + lane;
        const float* wr[NCAND];
        #pragma unroll
        for (int q = 0; q < NCAND; q++) wr[q] = w + (size_t)cid[q] * D_DIM + lane;
        #pragma unroll 4
        for (int m = 0; m < D_DIM / 32; m++) {
            float xv = __ldg(xr + 32 * m);
            #pragma unroll
            for (int q = 0; q < NCAND; q++)
                ex[q] = fmaf(xv, __ldg(wr[q] + 32 * m), ex[q]);
        }
        #pragma unroll
        for (int o = 16; o; o >>= 1)
            #pragma unroll
            for (int q = 0; q < NCAND; q++)
                ex[q] += __shfl_xor_sync(FULL, ex[q], o);

        int ids[NCAND]; float vs[NCAND];
        #pragma unroll
        for (int q = 0; q < NCAND; q++) { ids[q] = cid[q]; vs[q] = ex[q]; }
        #pragma unroll
        for (int a = 0; a < NCAND - 1; a++)
            #pragma unroll
            for (int b = 0; b < NCAND - 1 - a; b++) {
                bool sw = (vs[b + 1] > vs[b]) ||
                          (vs[b + 1] == vs[b] && ids[b + 1] < ids[b]);
                if (sw) {
                    float tv = vs[b]; vs[b] = vs[b + 1]; vs[b + 1] = tv;
                    int ti = ids[b]; ids[b] = ids[b + 1]; ids[b + 1] = ti;
                }
            }
        int nbi = ids[0], nsi = ids[1];

        float q0 = __shfl_sync(FULL, p0, nbi & 31);
        float q1 = __shfl_sync(FULL, p1, nbi & 31);
        float bvv = (nbi < 32) ? q0 : q1;
        q0 = __shfl_sync(FULL, p0, nsi & 31);
        q1 = __shfl_sync(FULL, p1, nsi & 31);
        float sv = (nsi < 32) ? q0 : q1;
        float tsum = bvv + sv;
        float pn1 = bvv / tsum, pn2 = sv / tsum;

        if (lane == 0) {
            size_t rowL = (size_t)n * E_DIM;
            out[rowL + pbi] = 0.f;      out[rowL + psi] = 0.f;
            out[NE + rowL + pbi] = 0.f; out[NE + rowL + psi] = 0.f;
            out[rowL + nbi] = pn1;      out[rowL + nsi] = pn2;
            out[NE + rowL + nbi] = pn1; out[NE + rowL + nsi] = pn2;
            size_t o5 = 4 * NE + 1 + (size_t)n * 2;
            out[o5] = (float)nbi; out[o5 + 1] = (float)nsi;
            size_t o6 = 4 * NE + 1 + (size_t)N * 2 + (size_t)n * 2;
            out[o6] = pn1; out[o6 + 1] = pn2;
        }
    }

    __syncthreads();
    __threadfence();
    if (tid == 0) {
        unsigned int d = atomicAdd(&g_done, 1u);
        if (d == (unsigned int)(gridDim.x - 1)) { g_qsize = 0; g_done = 0; }
    }
}

extern "C" void kernel_launch(void* const* d_in, const int* in_sizes, int n_in,
                              void* d_out, int out_size)
{
    const float* x = (const float*)d_in[0];   // [N, 2048]
    const float* w = (const float*)d_in[1];   // [64, 2048]
    float* out = (float*)d_out;

    int N = in_sizes[0] / D_DIM;              // 16384
    int nBlk = (N + BM - 1) / BM;             // 128

    cudaFuncSetAttribute(router_fused_kernel,
                         cudaFuncAttributeMaxDynamicSharedMemorySize, DSMEM_BYTES);

    router_fused_kernel<<<nBlk, NTH_G, DSMEM_BYTES>>>(x, w, out, N);
    router_rescue_kernel<<<128, 256>>>(x, w, out, N);
}

// round 17
// speedup vs baseline: 8.2620x; 1.2932x over previous
#include <cuda_runtime.h>
#include <cuda_fp16.h>
#include <math.h>
#include <stdint.h>

// Qwen2.5 MoE expert router — Round 17: fused fp16-HMMA GEMM + thread-per-token
// epilogue (BKT=128 double-buffered, 16 syncs), float4-vectorized warp rescue.
// out layout (fp32, reference return order):
//   [0, NE) dispatch | [NE, 2NE) combine | [2NE, 3NE) logits | [3NE, 4NE) probs
//   [4NE] aux_loss | [4NE+1, +2N) top_k_idx (float) | next 2N: top_k_probs_norm

#define D_DIM 2048
#define E_DIM 64
#define BM 128
#define BKT 128
#define NKT (D_DIM / BKT)      // 16
#define NTH_G 512
#define GAP_TH 2e-4f
#define NCAND 6

#define ROW_BYTES 272          // 256B fp16 data + 16B pad (36-word ≡ 4 mod 32: conflict-free)
#define SB_OFF (BM * ROW_BYTES)                            // 34816 (within buf)
#define BUF_BYTES (BM * ROW_BYTES + E_DIM * ROW_BYTES)     // 52224
#define DSMEM_BYTES (2 * BUF_BYTES)                        // 104448
#define LSTR 68                                            // floats; 16B-aligned rows

__device__ __forceinline__ uint32_t smem_u32(const void* p) {
    uint32_t a;
    asm("{ .reg .u64 t; cvta.to.shared.u64 t, %1; cvt.u32.u64 %0, t; }" : "=r"(a) : "l"(p));
    return a;
}
__device__ __forceinline__ void ldsm_x4(uint32_t* r, uint32_t addr) {
    asm volatile("ldmatrix.sync.aligned.m8n8.x4.shared.b16 {%0,%1,%2,%3}, [%4];"
                 : "=r"(r[0]), "=r"(r[1]), "=r"(r[2]), "=r"(r[3]) : "r"(addr));
}
__device__ __forceinline__ void mma_f16(float* d, const uint32_t* a,
                                        uint32_t b0, uint32_t b1) {
    asm volatile("mma.sync.aligned.m16n8k16.row.col.f32.f16.f16.f32 "
                 "{%0,%1,%2,%3}, {%4,%5,%6,%7}, {%8,%9}, {%0,%1,%2,%3};"
                 : "+f"(d[0]), "+f"(d[1]), "+f"(d[2]), "+f"(d[3])
                 : "r"(a[0]), "r"(a[1]), "r"(a[2]), "r"(a[3]), "r"(b0), "r"(b1));
}
__device__ __forceinline__ uint32_t pack_half2(float lo, float hi) {
    __half2 h = __floats2half2_rn(lo, hi);
    return *reinterpret_cast<uint32_t*>(&h);
}

__device__ float g_partials[128 * E_DIM];
__device__ unsigned int g_count = 0;
__device__ int g_queue[16384];
__device__ unsigned int g_qsize = 0;
__device__ unsigned int g_done = 0;

// ============ Kernel 1: fused GEMM + epilogue ============
__global__ __launch_bounds__(NTH_G, 1)
void router_fused_kernel(const float* __restrict__ x,
                         const float* __restrict__ w,
                         float* __restrict__ out,
                         int N)
{
    extern __shared__ char dsmem[];
    __shared__ float sAux[8 * E_DIM];
    __shared__ float sq[E_DIM];
    __shared__ int sIsLast;

    const uint32_t smem_b = smem_u32(dsmem);
    const int tid = threadIdx.x;
    const int wid = tid >> 5;
    const int lane = tid & 31;
    const int n0 = blockIdx.x * BM;
    const size_t NE = (size_t)N * E_DIM;
    const unsigned FULL = 0xffffffffu;

    const int mw = wid & 3;
    const int nw = wid >> 2;

    const uint32_t aRowLo = (uint32_t)((mw * 32 + (lane & 15)) * ROW_BYTES
                                       + (lane >> 4) * 16);
    const uint32_t aRowHi = aRowLo + 16 * ROW_BYTES;
    const uint32_t bOff = (uint32_t)((nw * 16 + ((lane >> 4) & 1) * 8 + (lane & 7)) * ROW_BYTES
                                     + ((lane >> 3) & 1) * 16);

    // staging: A 4096 float4/tile -> 8/thread; B 2048 float4/tile -> 4/thread
    float4 v[8];
    float4 wb[4];

    float acc[2][2][4];
    #pragma unroll
    for (int i = 0; i < 2; i++)
        #pragma unroll
        for (int j = 0; j < 2; j++)
            #pragma unroll
            for (int q = 0; q < 4; q++) acc[i][j][q] = 0.f;

    // ---- load tile 0 ----
    #pragma unroll
    for (int p = 0; p < 8; p++) {
        int idx = tid + NTH_G * p;
        int row = idx >> 5, c = idx & 31;
        int n = n0 + row; if (n > N - 1) n = N - 1;
        v[p] = *reinterpret_cast<const float4*>(x + (size_t)n * D_DIM + c * 4);
    }
    #pragma unroll
    for (int p = 0; p < 4; p++) {
        int idx = tid + NTH_G * p;
        int row = idx >> 5, c = idx & 31;
        wb[p] = *reinterpret_cast<const float4*>(w + (size_t)row * D_DIM + c * 4);
    }

    // ---- store tile 0 -> buf0, then issue loads for tile 1 ----
    {
        char* base = dsmem;
        #pragma unroll
        for (int p = 0; p < 8; p++) {
            int idx = tid + NTH_G * p;
            int row = idx >> 5, c = idx & 31;
            float4 f = v[p];
            *reinterpret_cast<uint2*>(base + (uint32_t)(row * ROW_BYTES + c * 8)) =
                make_uint2(pack_half2(f.x, f.y), pack_half2(f.z, f.w));
        }
        #pragma unroll
        for (int p = 0; p < 4; p++) {
            int idx = tid + NTH_G * p;
            int row = idx >> 5, c = idx & 31;
            float4 f = wb[p];
            *reinterpret_cast<uint2*>(base + SB_OFF + (uint32_t)(row * ROW_BYTES + c * 8)) =
                make_uint2(pack_half2(f.x, f.y), pack_half2(f.z, f.w));
        }
    }
    {
        const int kbase = BKT;
        #pragma unroll
        for (int p = 0; p < 8; p++) {
            int idx = tid + NTH_G * p;
            int row = idx >> 5, c = idx & 31;
            int n = n0 + row; if (n > N - 1) n = N - 1;
            v[p] = *reinterpret_cast<const float4*>(x + (size_t)n * D_DIM + kbase + c * 4);
        }
        #pragma unroll
        for (int p = 0; p < 4; p++) {
            int idx = tid + NTH_G * p;
            int row = idx >> 5, c = idx & 31;
            wb[p] = *reinterpret_cast<const float4*>(w + (size_t)row * D_DIM + kbase + c * 4);
        }
    }
    __syncthreads();

    // ---- main loop: 1 sync per ktile ----
    for (int kt = 0; kt < NKT; kt++) {
        if (kt + 1 < NKT) {
            char* base = dsmem + ((kt + 1) & 1) * BUF_BYTES;
            #pragma unroll
            for (int p = 0; p < 8; p++) {
                int idx = tid + NTH_G * p;
                int row = idx >> 5, c = idx & 31;
                float4 f = v[p];
                *reinterpret_cast<uint2*>(base + (uint32_t)(row * ROW_BYTES + c * 8)) =
                    make_uint2(pack_half2(f.x, f.y), pack_half2(f.z, f.w));
            }
            #pragma unroll
            for (int p = 0; p < 4; p++) {
                int idx = tid + NTH_G * p;
                int row = idx >> 5, c = idx & 31;
                float4 f = wb[p];
                *reinterpret_cast<uint2*>(base + SB_OFF + (uint32_t)(row * ROW_BYTES + c * 8)) =
                    make_uint2(pack_half2(f.x, f.y), pack_half2(f.z, f.w));
            }
        }
        if (kt + 2 < NKT) {
            const int kbase = (kt + 2) * BKT;
            #pragma unroll
            for (int p = 0; p < 8; p++) {
                int idx = tid + NTH_G * p;
                int row = idx >> 5, c = idx & 31;
                int n = n0 + row; if (n > N - 1) n = N - 1;
                v[p] = *reinterpret_cast<const float4*>(x + (size_t)n * D_DIM + kbase + c * 4);
            }
            #pragma unroll
            for (int p = 0; p < 4; p++) {
                int idx = tid + NTH_G * p;
                int row = idx >> 5, c = idx & 31;
                wb[p] = *reinterpret_cast<const float4*>(w + (size_t)row * D_DIM + kbase + c * 4);
            }
        }

        // compute tile kt from buf[kt&1]: 8 k16-steps
        const uint32_t bb = smem_b + (kt & 1) * BUF_BYTES;
        const uint32_t aLo = bb + aRowLo;
        const uint32_t aHi = bb + aRowHi;
        const uint32_t bAd = bb + SB_OFF + bOff;
        #pragma unroll
        for (int j = 0; j < 8; j++) {
            uint32_t faL[4], faH[4], fb[4];
            ldsm_x4(faL, aLo + j * 32);
            ldsm_x4(faH, aHi + j * 32);
            ldsm_x4(fb, bAd + j * 32);
            mma_f16(acc[0][0], faL, fb[0], fb[1]);
            mma_f16(acc[0][1], faL, fb[2], fb[3]);
            mma_f16(acc[1][0], faH, fb[0], fb[1]);
            mma_f16(acc[1][1], faH, fb[2], fb[3]);
        }
        __syncthreads();
    }

    // ---- fragments -> smem Lg (aliases buffers) ----
    float* Lg = reinterpret_cast<float*>(dsmem);
    #pragma unroll
    for (int mh = 0; mh < 2; mh++)
        #pragma unroll
        for (int nh = 0; nh < 2; nh++) {
            int r = mw * 32 + 16 * mh + (lane >> 2);
            int c = nw * 16 + 8 * nh + 2 * (lane & 3);
            *reinterpret_cast<float2*>(&Lg[r * LSTR + c]) =
                make_float2(acc[mh][nh][0], acc[mh][nh][1]);
            *reinterpret_cast<float2*>(&Lg[(r + 8) * LSTR + c]) =
                make_float2(acc[mh][nh][2], acc[mh][nh][3]);
        }
    __syncthreads();

    // ---- coalesced logits store ----
    #pragma unroll
    for (int p = 0; p < 4; p++) {
        int idx = tid + NTH_G * p;
        int tok = idx >> 4, c4 = idx & 15;
        float4 f = *reinterpret_cast<const float4*>(&Lg[tok * LSTR + c4 * 4]);
        *reinterpret_cast<float4*>(out + 2 * NE + (size_t)(n0 + tok) * E_DIM + c4 * 4) = f;
    }

    // ---- per-token softmax + top-3 scan (tid < 128) ----
    float v1 = -1.f, v2 = -1.f, v3 = -1.f;
    int i1 = 0, i2 = 0;
    float pn1 = 0.f, pn2 = 0.f;
    if (tid < BM) {
        float mx = -1e30f;
        #pragma unroll
        for (int c = 0; c < 16; c++) {
            float4 f = *reinterpret_cast<const float4*>(&Lg[tid * LSTR + c * 4]);
            mx = fmaxf(mx, fmaxf(fmaxf(f.x, f.y), fmaxf(f.z, f.w)));
        }
        float s = 0.f;
        #pragma unroll
        for (int c = 0; c < 16; c++) {
            float4 f = *reinterpret_cast<float4*>(&Lg[tid * LSTR + c * 4]);
            f.x = expf(f.x - mx); f.y = expf(f.y - mx);
            f.z = expf(f.z - mx); f.w = expf(f.w - mx);
            s += (f.x + f.y) + (f.z + f.w);
            *reinterpret_cast<float4*>(&Lg[tid * LSTR + c * 4]) = f;
        }
        float inv = 1.f / s;
        #pragma unroll
        for (int c = 0; c < 16; c++) {
            float4 f = *reinterpret_cast<float4*>(&Lg[tid * LSTR + c * 4]);
            f.x *= inv; f.y *= inv; f.z *= inv; f.w *= inv;
            float pv[4] = {f.x, f.y, f.z, f.w};
            #pragma unroll
            for (int j = 0; j < 4; j++) {
                float p = pv[j]; int ci = c * 4 + j;
                if (p > v1)      { v3 = v2; v2 = v1; i2 = i1; v1 = p; i1 = ci; }
                else if (p > v2) { v3 = v2; v2 = p; i2 = ci; }
                else if (p > v3) { v3 = p; }
            }
            *reinterpret_cast<float4*>(&Lg[tid * LSTR + c * 4]) = f;
        }
        float tsum = v1 + v2;
        pn1 = v1 / tsum; pn2 = v2 / tsum;

        int n = n0 + tid;
        size_t o5 = 4 * NE + 1 + (size_t)n * 2;
        out[o5] = (float)i1; out[o5 + 1] = (float)i2;
        size_t o6 = 4 * NE + 1 + (size_t)N * 2 + (size_t)n * 2;
        out[o6] = pn1; out[o6 + 1] = pn2;

        bool flag = (v1 - v2 < GAP_TH) || (v2 - v3 < GAP_TH);
        unsigned mask = __ballot_sync(FULL, flag);
        if (mask) {
            int ldr = __ffs(mask) - 1;
            unsigned base = 0;
            if (lane == ldr) base = atomicAdd(&g_qsize, (unsigned)__popc(mask));
            base = __shfl_sync(FULL, base, ldr);
            if (flag) {
                int pos = __popc(mask & ((1u << lane) - 1u));
                g_queue[base + pos] = n;
            }
        }
    }
    __syncthreads();

    // ---- coalesced probs store + aux column sums ----
    #pragma unroll
    for (int p = 0; p < 4; p++) {
        int idx = tid + NTH_G * p;
        int tok = idx >> 4, c4 = idx & 15;
        float4 f = *reinterpret_cast<const float4*>(&Lg[tok * LSTR + c4 * 4]);
        *reinterpret_cast<float4*>(out + 3 * NE + (size_t)(n0 + tok) * E_DIM + c4 * 4) = f;
    }
    {
        int e = tid & 63, g = tid >> 6;   // 8 groups x 16 rows
        float a = 0.f;
        #pragma unroll
        for (int r = 0; r < 16; r++)
            a += Lg[(g * 16 + r) * LSTR + e];
        sAux[g * E_DIM + e] = a;
    }
    __syncthreads();

    // ---- dispatch rows: zero + scatter, then coalesced store ----
    if (tid < BM) {
        #pragma unroll
        for (int c = 0; c < 16; c++)
            *reinterpret_cast<float4*>(&Lg[tid * LSTR + c * 4]) =
                make_float4(0.f, 0.f, 0.f, 0.f);
        Lg[tid * LSTR + i1] = pn1;
        Lg[tid * LSTR + i2] = pn2;
    }
    __syncthreads();
    #pragma unroll
    for (int p = 0; p < 4; p++) {
        int idx = tid + NTH_G * p;
        int tok = idx >> 4, c4 = idx & 15;
        float4 f = *reinterpret_cast<const float4*>(&Lg[tok * LSTR + c4 * 4]);
        *reinterpret_cast<float4*>(out + (size_t)(n0 + tok) * E_DIM + c4 * 4) = f;
        *reinterpret_cast<float4*>(out + NE + (size_t)(n0 + tok) * E_DIM + c4 * 4) = f;
    }

    // ---- aux partials + last-block reduction ----
    if (tid < E_DIM) {
        float ssum = 0.f;
        #pragma unroll
        for (int g = 0; g < 8; g++) ssum += sAux[g * E_DIM + tid];
        g_partials[blockIdx.x * E_DIM + tid] = ssum;
    }
    __threadfence();
    if (tid == 0) {
        unsigned int prev = atomicAdd(&g_count, 1u);
        sIsLast = (prev == (unsigned int)(gridDim.x - 1)) ? 1 : 0;
    }
    __syncthreads();

    if (sIsLast) {
        __threadfence();
        int e = tid & 63, q = tid >> 6;
        float sum = 0.f;
        for (int b = q; b < (int)gridDim.x; b += 8) sum += g_partials[b * E_DIM + e];
        sAux[q * E_DIM + e] = sum;
        __syncthreads();
        if (tid < E_DIM) {
            float t = 0.f;
            #pragma unroll
            for (int g = 0; g < 8; g++) t += sAux[g * E_DIM + tid];
            float m = t / (float)N;
            sq[tid] = m * m;
        }
        __syncthreads();
        if (tid == 0) {
            float a = 0.f;
            #pragma unroll
            for (int i = 0; i < E_DIM; i++) a += sq[i];
            out[4 * NE] = a;
            g_count = 0;
        }
    }
}

// ============ Kernel 2: warp-cooperative exact rescue (float4) ============
__global__ __launch_bounds__(256)
void router_rescue_kernel(const float* __restrict__ x,
                          const float* __restrict__ w,
                          float* __restrict__ out,
                          int N)
{
    const int tid = threadIdx.x;
    const int lane = tid & 31;
    const int gw = (blockIdx.x * 256 + tid) >> 5;
    const int nwarps = (gridDim.x * 256) >> 5;
    const size_t NE = (size_t)N * E_DIM;
    const float NEG_INF = __int_as_float(0xff800000);
    const unsigned FULL = 0xffffffffu;

    const int qn = (int)g_qsize;

    for (int qi = gw; qi < qn; qi += nwarps) {
        int n = g_queue[qi];
        float p0 = out[3 * NE + (size_t)n * E_DIM + lane];
        float p1 = out[3 * NE + (size_t)n * E_DIM + lane + 32];

        int cid[NCAND]; float m0v = p0, m1v = p1;
        #pragma unroll
        for (int rko = 0; rko < NCAND; rko++) {
            float bv; int bix;
            if (m0v >= m1v) { bv = m0v; bix = lane; } else { bv = m1v; bix = lane + 32; }
            #pragma unroll
            for (int o = 16; o; o >>= 1) {
                float ov = __shfl_xor_sync(FULL, bv, o);
                int   oi = __shfl_xor_sync(FULL, bix, o);
                if (ov > bv || (ov == bv && oi < bix)) { bv = ov; bix = oi; }
            }
            cid[rko] = bix;
            if (lane == bix) m0v = NEG_INF;
            if (lane + 32 == bix) m1v = NEG_INF;
        }
        int pbi = cid[0], psi = cid[1];

        // exact fp32 logits for candidates — float4 vectorized, lane-strided
        float ex[NCAND];
        #pragma unroll
        for (int q = 0; q < NCAND; q++) ex[q] = 0.f;
        const float4* x4 = reinterpret_cast<const float4*>(x + (size_t)n * D_DIM);
        const float4* w4[NCAND];
        #pragma unroll
        for (int q = 0; q < NCAND; q++)
            w4[q] = reinterpret_cast<const float4*>(w + (size_t)cid[q] * D_DIM);
        #pragma unroll 4
        for (int m = 0; m < D_DIM / 128; m++) {       // 16 iters
            float4 xv = __ldg(x4 + lane + 32 * m);
            #pragma unroll
            for (int q = 0; q < NCAND; q++) {
                float4 wvq = __ldg(w4[q] + lane + 32 * m);
                ex[q] = fmaf(xv.x, wvq.x, ex[q]);
                ex[q] = fmaf(xv.y, wvq.y, ex[q]);
                ex[q] = fmaf(xv.z, wvq.z, ex[q]);
                ex[q] = fmaf(xv.w, wvq.w, ex[q]);
            }
        }
        #pragma unroll
        for (int o = 16; o; o >>= 1)
            #pragma unroll
            for (int q = 0; q < NCAND; q++)
                ex[q] += __shfl_xor_sync(FULL, ex[q], o);

        int ids[NCAND]; float vs[NCAND];
        #pragma unroll
        for (int q = 0; q < NCAND; q++) { ids[q] = cid[q]; vs[q] = ex[q]; }
        #pragma unroll
        for (int a = 0; a < NCAND - 1; a++)
            #pragma unroll
            for (int b = 0; b < NCAND - 1 - a; b++) {
                bool sw = (vs[b + 1] > vs[b]) ||
                          (vs[b + 1] == vs[b] && ids[b + 1] < ids[b]);
                if (sw) {
                    float tv = vs[b]; vs[b] = vs[b + 1]; vs[b + 1] = tv;
                    int ti = ids[b]; ids[b] = ids[b + 1]; ids[b + 1] = ti;
                }
            }
        int nbi = ids[0], nsi = ids[1];

        float q0 = __shfl_sync(FULL, p0, nbi & 31);
        float q1 = __shfl_sync(FULL, p1, nbi & 31);
        float bvv = (nbi < 32) ? q0 : q1;
        q0 = __shfl_sync(FULL, p0, nsi & 31);
        q1 = __shfl_sync(FULL, p1, nsi & 31);
        float sv = (nsi < 32) ? q0 : q1;
        float tsum = bvv + sv;
        float pn1 = bvv / tsum, pn2 = sv / tsum;

        if (lane == 0) {
            size_t rowL = (size_t)n * E_DIM;
            out[rowL + pbi] = 0.f;      out[rowL + psi] = 0.f;
            out[NE + rowL + pbi] = 0.f; out[NE + rowL + psi] = 0.f;
            out[rowL + nbi] = pn1;      out[rowL + nsi] = pn2;
            out[NE + rowL + nbi] = pn1; out[NE + rowL + nsi] = pn2;
            size_t o5 = 4 * NE + 1 + (size_t)n * 2;
            out[o5] = (float)nbi; out[o5 + 1] = (float)nsi;
            size_t o6 = 4 * NE + 1 + (size_t)N * 2 + (size_t)n * 2;
            out[o6] = pn1; out[o6 + 1] = pn2;
        }
    }

    __syncthreads();
    __threadfence();
    if (tid == 0) {
        unsigned int d = atomicAdd(&g_done, 1u);
        if (d == (unsigned int)(gridDim.x - 1)) { g_qsize = 0; g_done = 0; }
    }
}

extern "C" void kernel_launch(void* const* d_in, const int* in_sizes, int n_in,
                              void* d_out, int out_size)
{
    const float* x = (const float*)d_in[0];   // [N, 2048]
    const float* w = (const float*)d_in[1];   // [64, 2048]
    float* out = (float*)d_out;

    int N = in_sizes[0] / D_DIM;              // 16384
    int nBlk = (N + BM - 1) / BM;             // 128

    cudaFuncSetAttribute(router_fused_kernel,
                         cudaFuncAttributeMaxDynamicSharedMemorySize, DSMEM_BYTES);

    router_fused_kernel<<<nBlk, NTH_G, DSMEM_BYTES>>>(x, w, out, N);
    router_rescue_kernel<<<128, 256>>>(x, w, out, N);
}